// round 1
// baseline (speedup 1.0000x reference)
#include <cuda_runtime.h>

#define BB 2
#define SS 2048
#define DM 2048
#define HH 16
#define HD 128
#define NROWS (BB*SS)

// Scratch (allocation-free rule: __device__ globals)
__device__ __align__(256) float g_q[BB*HH*SS*HD];
__device__ __align__(256) float g_k[BB*HH*SS*HD];
__device__ __align__(256) float g_v[BB*HH*SS*HD];
__device__ __align__(256) float g_y[NROWS*DM];

// ---------------------------------------------------------------------------
// C[m,n] = sum_k A[m,k] * W[n,k]   (both K-contiguous).
// M = 4096, N = 2048, K = 2048. 128x128 tile, BK=16, 256 threads, 8x8/thread
// (quadrant layout for conflict-free smem reads).
// HEADOUT: scatter C into (B,H,S,hd) layout (head h == column tile index).
// ---------------------------------------------------------------------------
template<bool HEADOUT>
__global__ __launch_bounds__(256, 2)
void gemm_nt(const float* __restrict__ A, const float* __restrict__ W,
             float* __restrict__ C)
{
    __shared__ float As[16][128];
    __shared__ float Bs[16][128];
    const int tid = threadIdx.x;
    const int tx = tid & 15, ty = tid >> 4;
    const int bm = blockIdx.y * 128;
    const int bn = blockIdx.x * 128;
    const int lr = tid >> 2;
    const int lc = (tid & 3) << 2;
    const float* Ap = A + (size_t)(bm + lr) * DM + lc;
    const float* Wp = W + (size_t)(bn + lr) * DM + lc;
    float acc[8][8] = {};

    for (int k0 = 0; k0 < DM; k0 += 16) {
        float4 a0 = *(const float4*)(Ap + k0);
        float4 a1 = *(const float4*)(Ap + (size_t)64 * DM + k0);
        float4 b0 = *(const float4*)(Wp + k0);
        float4 b1 = *(const float4*)(Wp + (size_t)64 * DM + k0);
        __syncthreads();
        As[lc+0][lr]    = a0.x; As[lc+1][lr]    = a0.y; As[lc+2][lr]    = a0.z; As[lc+3][lr]    = a0.w;
        As[lc+0][lr+64] = a1.x; As[lc+1][lr+64] = a1.y; As[lc+2][lr+64] = a1.z; As[lc+3][lr+64] = a1.w;
        Bs[lc+0][lr]    = b0.x; Bs[lc+1][lr]    = b0.y; Bs[lc+2][lr]    = b0.z; Bs[lc+3][lr]    = b0.w;
        Bs[lc+0][lr+64] = b1.x; Bs[lc+1][lr+64] = b1.y; Bs[lc+2][lr+64] = b1.z; Bs[lc+3][lr+64] = b1.w;
        __syncthreads();
        #pragma unroll
        for (int kk = 0; kk < 16; kk++) {
            float a[8], b[8];
            *(float4*)&a[0] = *(const float4*)&As[kk][ty*4];
            *(float4*)&a[4] = *(const float4*)&As[kk][64 + ty*4];
            *(float4*)&b[0] = *(const float4*)&Bs[kk][tx*4];
            *(float4*)&b[4] = *(const float4*)&Bs[kk][64 + tx*4];
            #pragma unroll
            for (int i = 0; i < 8; i++)
                #pragma unroll
                for (int j = 0; j < 8; j++)
                    acc[i][j] += a[i]*b[j];
        }
    }

    #pragma unroll
    for (int i = 0; i < 8; i++) {
        const int r = (i < 4) ? (ty*4 + i) : (64 + ty*4 + i - 4);
        const int m = bm + r;
        #pragma unroll
        for (int jh = 0; jh < 2; jh++) {
            const int cb = jh ? (64 + tx*4) : (tx*4);
            float4 v = make_float4(acc[i][jh*4+0], acc[i][jh*4+1],
                                   acc[i][jh*4+2], acc[i][jh*4+3]);
            if (HEADOUT) {
                const int b = m / SS, s = m % SS;
                const int h = bn / HD;           // one head per 128-col tile
                *(float4*)(C + ((size_t)((b*HH + h)*SS + s))*HD + cb) = v;
            } else {
                *(float4*)(C + (size_t)m*DM + bn + cb) = v;
            }
        }
    }
}

// ---------------------------------------------------------------------------
// Per-(b,h,s) row of 128: RMS norm over head dim, then RoPE.
// blockIdx.y: 0 = q, 1 = k. cos/sin indexed by (b, s, hd) (broadcast over h).
// ---------------------------------------------------------------------------
__global__ void rms_rope_kernel(const float* __restrict__ cq, const float* __restrict__ sq,
                                const float* __restrict__ ck, const float* __restrict__ sk,
                                const float* __restrict__ qw, const float* __restrict__ kw)
{
    const int row = blockIdx.x;            // (b*HH + h)*SS + s
    const int isk = blockIdx.y;
    float* data     = isk ? g_k : g_q;
    const float* cp = isk ? ck : cq;
    const float* sp = isk ? sk : sq;
    const float* w  = isk ? kw : qw;
    const int tid = threadIdx.x;           // 0..127
    const int s = row % SS;
    const int b = row / (HH*SS);

    __shared__ float smv[HD];
    __shared__ float red[4];
    float v = data[(size_t)row*HD + tid];
    float s2 = v*v;
    #pragma unroll
    for (int o = 16; o; o >>= 1) s2 += __shfl_xor_sync(0xffffffffu, s2, o);
    if ((tid & 31) == 0) red[tid >> 5] = s2;
    __syncthreads();
    const float var = (red[0]+red[1]+red[2]+red[3]) * (1.0f/HD);
    const float qn = v * rsqrtf(var + 1e-6f) * w[tid];
    smv[tid] = qn;
    __syncthreads();
    const float rot = (tid < 64) ? -smv[tid+64] : smv[tid-64];
    const size_t ci = ((size_t)b*SS + s)*HD + tid;
    data[(size_t)row*HD + tid] = qn * cp[ci] + rot * sp[ci];
}

// ---------------------------------------------------------------------------
// Flash attention, fp32. One block = 64 queries of one (b,h).
// Qs/Ks stored k-major [128][64]; Vs row-major [64][128]; P row-major padded.
// Writes y in (B, S, H, hd) == (B, S, Dm) layout.
// ---------------------------------------------------------------------------
#define PS 68
#define FLASH_SMEM ((128*64 + 128*64 + 64*128 + 64*PS + 192)*4)

__global__ __launch_bounds__(256)
void flash_kernel()
{
    extern __shared__ float sm[];
    float* Qs = sm;                 // [128][64]
    float* Ks = Qs + 128*64;        // [128][64]
    float* Vs = Ks + 128*64;        // [64][128]
    float* Psm = Vs + 64*128;       // [64][PS]
    float* Mr = Psm + 64*PS;
    float* Lr = Mr + 64;
    float* Ar = Lr + 64;

    const int tid = threadIdx.x;
    const int tx = tid & 15, ty = tid >> 4;
    const int qb = blockIdx.x;
    const int bh = blockIdx.y;
    const size_t base = (size_t)bh * SS * HD;
    const float* Qg = g_q + base + (size_t)qb * 64 * HD;
    const float* Kg = g_k + base;
    const float* Vg = g_v + base;

    {   // load Q block transposed
        const int r = tid >> 2, c0 = (tid & 3) << 2;
        #pragma unroll
        for (int c = 0; c < 8; c++) {
            const int col = c0 + c*16;
            float4 v = *(const float4*)(Qg + (size_t)r*HD + col);
            Qs[(col+0)*64 + r] = v.x;
            Qs[(col+1)*64 + r] = v.y;
            Qs[(col+2)*64 + r] = v.z;
            Qs[(col+3)*64 + r] = v.w;
        }
    }
    if (tid < 64) { Mr[tid] = -1e30f; Lr[tid] = 0.f; }

    float O[4][8] = {};

    for (int kb = 0; kb < SS/64; kb++) {
        __syncthreads();
        {   // load K (transposed) + V (row-major) tiles
            const int r = tid >> 2, c0 = (tid & 3) << 2;
            const float* kp = Kg + (size_t)(kb*64 + r)*HD;
            const float* vp = Vg + (size_t)(kb*64 + r)*HD;
            #pragma unroll
            for (int c = 0; c < 8; c++) {
                const int col = c0 + c*16;
                float4 kv = *(const float4*)(kp + col);
                Ks[(col+0)*64 + r] = kv.x;
                Ks[(col+1)*64 + r] = kv.y;
                Ks[(col+2)*64 + r] = kv.z;
                Ks[(col+3)*64 + r] = kv.w;
                *(float4*)(Vs + (size_t)r*HD + col) = *(const float4*)(vp + col);
            }
        }
        __syncthreads();

        // S = Q @ K^T  (4x4 per thread)
        float Sacc[4][4] = {};
        #pragma unroll 8
        for (int k = 0; k < HD; k++) {
            float a[4], b[4];
            *(float4*)a = *(const float4*)(Qs + k*64 + ty*4);
            *(float4*)b = *(const float4*)(Ks + k*64 + tx*4);
            #pragma unroll
            for (int i = 0; i < 4; i++)
                #pragma unroll
                for (int j = 0; j < 4; j++)
                    Sacc[i][j] += a[i]*b[j];
        }
        const float sc = 0.08838834764831845f;  // 1/sqrt(128)
        #pragma unroll
        for (int i = 0; i < 4; i++) {
            float4 v = make_float4(Sacc[i][0]*sc, Sacc[i][1]*sc,
                                   Sacc[i][2]*sc, Sacc[i][3]*sc);
            *(float4*)(Psm + (ty*4+i)*PS + tx*4) = v;
        }
        __syncthreads();

        // online softmax: one thread per row
        if (tid < 64) {
            float* pr = Psm + tid*PS;
            const float mold = Mr[tid];
            float mx = mold;
            #pragma unroll 8
            for (int j = 0; j < 64; j++) mx = fmaxf(mx, pr[j]);
            const float alpha = __expf(mold - mx);
            float sum = 0.f;
            #pragma unroll 8
            for (int j = 0; j < 64; j++) {
                const float p = __expf(pr[j] - mx);
                pr[j] = p;
                sum += p;
            }
            Lr[tid] = Lr[tid]*alpha + sum;
            Mr[tid] = mx;
            Ar[tid] = alpha;
        }
        __syncthreads();

        // rescale O, then O += P @ V
        float al[4];
        #pragma unroll
        for (int i = 0; i < 4; i++) al[i] = Ar[ty*4+i];
        #pragma unroll
        for (int i = 0; i < 4; i++)
            #pragma unroll
            for (int j = 0; j < 8; j++) O[i][j] *= al[i];

        #pragma unroll 2
        for (int j0 = 0; j0 < 64; j0 += 4) {
            float p[4][4];
            #pragma unroll
            for (int i = 0; i < 4; i++)
                *(float4*)p[i] = *(const float4*)(Psm + (ty*4+i)*PS + j0);
            #pragma unroll
            for (int jj = 0; jj < 4; jj++) {
                float vv[8];
                *(float4*)&vv[0] = *(const float4*)(Vs + (j0+jj)*HD + tx*4);
                *(float4*)&vv[4] = *(const float4*)(Vs + (j0+jj)*HD + 64 + tx*4);
                #pragma unroll
                for (int i = 0; i < 4; i++)
                    #pragma unroll
                    for (int c = 0; c < 8; c++)
                        O[i][c] += p[i][jj]*vv[c];
            }
        }
    }

    // write y in (B, S, H, hd) layout
    const int b = bh / HH, h = bh % HH;
    #pragma unroll
    for (int i = 0; i < 4; i++) {
        const int r = ty*4 + i;
        const float linv = 1.0f / Lr[r];
        const int s = qb*64 + r;
        float* yp = g_y + ((size_t)(b*SS + s)*HH + h)*HD;
        float4 o0 = make_float4(O[i][0]*linv, O[i][1]*linv, O[i][2]*linv, O[i][3]*linv);
        float4 o1 = make_float4(O[i][4]*linv, O[i][5]*linv, O[i][6]*linv, O[i][7]*linv);
        *(float4*)(yp + tx*4) = o0;
        *(float4*)(yp + 64 + tx*4) = o1;
    }
}

// ---------------------------------------------------------------------------
extern "C" void kernel_launch(void* const* d_in, const int* in_sizes, int n_in,
                              void* d_out, int out_size)
{
    const float* x   = (const float*)d_in[0];
    const float* ctx = (const float*)d_in[1];
    const float* cq  = (const float*)d_in[2];
    const float* sq  = (const float*)d_in[3];
    const float* ck  = (const float*)d_in[4];
    const float* sk  = (const float*)d_in[5];
    const float* Wq  = (const float*)d_in[6];
    const float* Wk  = (const float*)d_in[7];
    const float* Wv  = (const float*)d_in[8];
    const float* Wo  = (const float*)d_in[9];
    const float* qw  = (const float*)d_in[10];
    const float* kw  = (const float*)d_in[11];
    float* out = (float*)d_out;

    float *gq, *gk, *gv, *gy;
    cudaGetSymbolAddress((void**)&gq, g_q);
    cudaGetSymbolAddress((void**)&gk, g_k);
    cudaGetSymbolAddress((void**)&gv, g_v);
    cudaGetSymbolAddress((void**)&gy, g_y);

    cudaFuncSetAttribute(flash_kernel,
                         cudaFuncAttributeMaxDynamicSharedMemorySize, FLASH_SMEM);

    dim3 gg(DM/128, NROWS/128);   // (16, 32)
    gemm_nt<true><<<gg, 256>>>(x,   Wq, gq);
    gemm_nt<true><<<gg, 256>>>(ctx, Wk, gk);
    gemm_nt<true><<<gg, 256>>>(ctx, Wv, gv);
    rms_rope_kernel<<<dim3(BB*HH*SS, 2), HD>>>(cq, sq, ck, sk, qw, kw);
    flash_kernel<<<dim3(SS/64, BB*HH), 256, FLASH_SMEM>>>();
    gemm_nt<false><<<gg, 256>>>(gy, Wo, out);
}

// round 3
// speedup vs baseline: 1.4869x; 1.4869x over previous
#include <cuda_runtime.h>
#include <cuda_bf16.h>
#include <cstdint>

#define BB 2
#define SS 2048
#define DM 2048
#define HH 16
#define HD 128
#define NROWS (BB*SS)

// ---------------------------------------------------------------------------
// Helpers (plain sm_80-era PTX only: ldmatrix / mma.sync / cp.async)
// ---------------------------------------------------------------------------
__device__ __forceinline__ uint32_t smem_to_u32(const void* p) {
    uint32_t a;
    asm("{ .reg .u64 t; cvta.to.shared.u64 t, %1; cvt.u32.u64 %0, t; }" : "=r"(a) : "l"(p));
    return a;
}
#define SWZ128(off) ((off) ^ (((off) >> 3) & 0x70))

__device__ __forceinline__ void cpa16(uint32_t s, const void* g) {
    asm volatile("cp.async.cg.shared.global [%0], [%1], 16;" :: "r"(s), "l"(g));
}
#define CP_COMMIT() asm volatile("cp.async.commit_group;" ::: "memory")
#define CP_WAIT1()  asm volatile("cp.async.wait_group 1;" ::: "memory")
#define CP_WAIT0()  asm volatile("cp.async.wait_group 0;" ::: "memory")

__device__ __forceinline__ void ldmx4(uint32_t& r0, uint32_t& r1, uint32_t& r2, uint32_t& r3,
                                      uint32_t addr) {
    asm volatile("ldmatrix.sync.aligned.m8n8.x4.shared.b16 {%0,%1,%2,%3}, [%4];"
                 : "=r"(r0), "=r"(r1), "=r"(r2), "=r"(r3) : "r"(addr));
}
__device__ __forceinline__ void mma16816(float* c, const uint32_t* a, const uint32_t* b) {
    asm volatile("mma.sync.aligned.m16n8k16.row.col.f32.bf16.bf16.f32 "
                 "{%0,%1,%2,%3}, {%4,%5,%6,%7}, {%8,%9}, {%0,%1,%2,%3};"
                 : "+f"(c[0]), "+f"(c[1]), "+f"(c[2]), "+f"(c[3])
                 : "r"(a[0]), "r"(a[1]), "r"(a[2]), "r"(a[3]), "r"(b[0]), "r"(b[1]));
}

// ---------------------------------------------------------------------------
// Device scratch
// ---------------------------------------------------------------------------
__device__ __align__(256) float g_q[(size_t)BB*HH*SS*HD];
__device__ __align__(256) float g_k[(size_t)BB*HH*SS*HD];
__device__ __align__(256) float g_v[(size_t)BB*HH*SS*HD];
__device__ __align__(256) __nv_bfloat16 g_xhi[(size_t)NROWS*DM];
__device__ __align__(256) __nv_bfloat16 g_xlo[(size_t)NROWS*DM];
__device__ __align__(256) __nv_bfloat16 g_chi[(size_t)NROWS*DM];
__device__ __align__(256) __nv_bfloat16 g_clo[(size_t)NROWS*DM];
__device__ __align__(256) __nv_bfloat16 g_wqh[DM*DM], g_wql[DM*DM];
__device__ __align__(256) __nv_bfloat16 g_wkh[DM*DM], g_wkl[DM*DM];
__device__ __align__(256) __nv_bfloat16 g_wvh[DM*DM], g_wvl[DM*DM];
__device__ __align__(256) __nv_bfloat16 g_woh[DM*DM], g_wol[DM*DM];
__device__ __align__(256) __nv_bfloat16 g_yhi[(size_t)NROWS*DM];
__device__ __align__(256) __nv_bfloat16 g_ylo[(size_t)NROWS*DM];

// ---------------------------------------------------------------------------
// fp32 -> (hi = truncated bf16 [exact], lo = RN bf16 of residual)
// ---------------------------------------------------------------------------
__global__ void cvt_kernel(const float* __restrict__ src, __nv_bfloat16* __restrict__ hi,
                           __nv_bfloat16* __restrict__ lo, int n4)
{
    int i = blockIdx.x*blockDim.x + threadIdx.x;
    if (i >= n4) return;
    float4 v = ((const float4*)src)[i];
    uint32_t bx = __float_as_uint(v.x), by = __float_as_uint(v.y);
    uint32_t bz = __float_as_uint(v.z), bw = __float_as_uint(v.w);
    uint32_t h01 = __byte_perm(bx, by, 0x7632);
    uint32_t h23 = __byte_perm(bz, bw, 0x7632);
    float rx = v.x - __uint_as_float(bx & 0xffff0000u);
    float ry = v.y - __uint_as_float(by & 0xffff0000u);
    float rz = v.z - __uint_as_float(bz & 0xffff0000u);
    float rw = v.w - __uint_as_float(bw & 0xffff0000u);
    __nv_bfloat162 l01 = __float22bfloat162_rn(make_float2(rx, ry));
    __nv_bfloat162 l23 = __float22bfloat162_rn(make_float2(rz, rw));
    ((uint2*)hi)[i] = make_uint2(h01, h23);
    uint2 lw2;
    lw2.x = *(uint32_t*)&l01;
    lw2.y = *(uint32_t*)&l23;
    ((uint2*)lo)[i] = lw2;
}

// ---------------------------------------------------------------------------
// mma.sync bf16-pair GEMM: C[m,n] = sum_k A[m,k]*W[n,k]  (both K-contiguous)
// CTA 128x128, 8 warps (2m x 4n), warp tile 64x32, KC=64 double-buffered
// cp.async, SW128-swizzled smem, 3 HMMA products (hh, hl, lh) per tile.
// ---------------------------------------------------------------------------
#define KC 64
#define NSTG (DM/KC)
#define AH_OFF 0
#define AL_OFF 16384
#define BH_OFF 32768
#define BL_OFF 49152
#define STG_BYTES 65536
#define GEMM_DSMEM (2*STG_BYTES + 1024)

template<bool HEADOUT>
__global__ __launch_bounds__(256, 1)
void gemm_mma(const __nv_bfloat16* __restrict__ Ah, const __nv_bfloat16* __restrict__ Al,
              const __nv_bfloat16* __restrict__ Bh, const __nv_bfloat16* __restrict__ Bl,
              float* __restrict__ C)
{
    extern __shared__ char dsm_raw[];
    const uint32_t raw_u = smem_to_u32(dsm_raw);
    const uint32_t sbase = (raw_u + 1023u) & ~1023u;   // 1024-align for swizzle

    const int tid = threadIdx.x;
    const int wid = tid >> 5;
    const int lane = tid & 31;
    const int warp_m = wid >> 2;        // 0..1  (64 rows)
    const int warp_n = wid & 3;         // 0..3  (32 cols)
    const int m0 = blockIdx.y * 128;
    const int n0 = blockIdx.x * 128;

    // prefetch assignment: row = tid>>1 (0..127), half = tid&1 (32 elems = 64B)
    const int prow = tid >> 1;
    const int phalf = tid & 1;
    const size_t gA = (size_t)(m0 + prow) * DM + phalf * 32;
    const size_t gB = (size_t)(n0 + prow) * DM + phalf * 32;

    float acc[4][4][4];
    #pragma unroll
    for (int i = 0; i < 4; i++)
        #pragma unroll
        for (int j = 0; j < 4; j++)
            #pragma unroll
            for (int r = 0; r < 4; r++) acc[i][j][r] = 0.f;

    // ---- prefetch stage 0
    {
        const uint32_t buf = sbase;
        #pragma unroll
        for (int c = 0; c < 4; c++) {
            const uint32_t sw = SWZ128((uint32_t)(prow*128 + (phalf*4 + c)*16));
            const size_t go = (size_t)c * 8;
            cpa16(buf + AH_OFF + sw, Ah + gA + go);
            cpa16(buf + AL_OFF + sw, Al + gA + go);
            cpa16(buf + BH_OFF + sw, Bh + gB + go);
            cpa16(buf + BL_OFF + sw, Bl + gB + go);
        }
        CP_COMMIT();
    }

    // ldmatrix base offsets (within a stage buffer)
    // A x4 tile: r = mrow + (lane&15), chunk = kchunk + (lane>>4)
    const int a_r = warp_m*64 + (lane & 15);
    const int a_cs = lane >> 4;
    // B x4 pair: row = nbase + ((lane>>4)<<3) + (lane&7), chunk = kchunk + ((lane>>3)&1)
    const int b_r = warp_n*32 + ((lane >> 4) << 3) + (lane & 7);
    const int b_cs = (lane >> 3) & 1;

    for (int s = 0; s < NSTG; s++) {
        if (s + 1 < NSTG) {
            const uint32_t buf = sbase + ((s+1) & 1) * STG_BYTES;
            const size_t ko = (size_t)(s+1) * KC;
            #pragma unroll
            for (int c = 0; c < 4; c++) {
                const uint32_t sw = SWZ128((uint32_t)(prow*128 + (phalf*4 + c)*16));
                const size_t go = ko + (size_t)c * 8;
                cpa16(buf + AH_OFF + sw, Ah + gA + go);
                cpa16(buf + AL_OFF + sw, Al + gA + go);
                cpa16(buf + BH_OFF + sw, Bh + gB + go);
                cpa16(buf + BL_OFF + sw, Bl + gB + go);
            }
            CP_COMMIT();
            CP_WAIT1();
        } else {
            CP_WAIT0();
        }
        __syncthreads();

        const uint32_t buf = sbase + (s & 1) * STG_BYTES;
        #pragma unroll
        for (int ks = 0; ks < 4; ks++) {
            const int kc = ks * 2;      // 16B-chunk index of this k16 step
            uint32_t ah[4][4], al_[4][4], bh[4][2], bl[4][2];
            #pragma unroll
            for (int mt = 0; mt < 4; mt++) {
                const uint32_t off = (uint32_t)((a_r + mt*16)*128 + (kc + a_cs)*16);
                ldmx4(ah[mt][0], ah[mt][1], ah[mt][2], ah[mt][3], buf + AH_OFF + SWZ128(off));
                ldmx4(al_[mt][0], al_[mt][1], al_[mt][2], al_[mt][3], buf + AL_OFF + SWZ128(off));
            }
            #pragma unroll
            for (int np = 0; np < 2; np++) {
                const uint32_t off = (uint32_t)((b_r + np*16)*128 + (kc + b_cs)*16);
                ldmx4(bh[np*2][0], bh[np*2][1], bh[np*2+1][0], bh[np*2+1][1],
                      buf + BH_OFF + SWZ128(off));
                ldmx4(bl[np*2][0], bl[np*2][1], bl[np*2+1][0], bl[np*2+1][1],
                      buf + BL_OFF + SWZ128(off));
            }
            #pragma unroll
            for (int mt = 0; mt < 4; mt++)
                #pragma unroll
                for (int nt = 0; nt < 4; nt++) {
                    mma16816(acc[mt][nt], ah[mt], bh[nt]);
                    mma16816(acc[mt][nt], ah[mt], bl[nt]);
                    mma16816(acc[mt][nt], al_[mt], bh[nt]);
                }
        }
        __syncthreads();
    }

    // ---- epilogue
    #pragma unroll
    for (int mt = 0; mt < 4; mt++) {
        const int mrow = m0 + warp_m*64 + mt*16 + (lane >> 2);
        #pragma unroll
        for (int half = 0; half < 2; half++) {
            const int m = mrow + half*8;
            float* base;
            if (HEADOUT) {
                const int b = m >> 11, sidx = m & (SS - 1);
                base = C + ((size_t)((b*HH + blockIdx.x)*SS + sidx))*HD;
            } else {
                base = C + (size_t)m*DM + n0;
            }
            #pragma unroll
            for (int nt = 0; nt < 4; nt++) {
                const int nn = warp_n*32 + nt*8 + 2*(lane & 3);
                float2 v = half ? make_float2(acc[mt][nt][2], acc[mt][nt][3])
                                : make_float2(acc[mt][nt][0], acc[mt][nt][1]);
                *(float2*)(base + nn) = v;
            }
        }
    }
}

// ---------------------------------------------------------------------------
// Per-(b,h,s) row of 128: RMS norm over head dim, then RoPE.
// ---------------------------------------------------------------------------
__global__ void rms_rope_kernel(const float* __restrict__ cq, const float* __restrict__ sq,
                                const float* __restrict__ ck, const float* __restrict__ sk,
                                const float* __restrict__ qw, const float* __restrict__ kw)
{
    const int row = blockIdx.x;
    const int isk = blockIdx.y;
    float* data     = isk ? g_k : g_q;
    const float* cp = isk ? ck : cq;
    const float* sp = isk ? sk : sq;
    const float* w  = isk ? kw : qw;
    const int tid = threadIdx.x;
    const int s = row % SS;
    const int b = row / (HH*SS);

    __shared__ float smv[HD];
    __shared__ float red[4];
    float v = data[(size_t)row*HD + tid];
    float s2 = v*v;
    #pragma unroll
    for (int o = 16; o; o >>= 1) s2 += __shfl_xor_sync(0xffffffffu, s2, o);
    if ((tid & 31) == 0) red[tid >> 5] = s2;
    __syncthreads();
    const float var = (red[0]+red[1]+red[2]+red[3]) * (1.0f/HD);
    const float qn = v * rsqrtf(var + 1e-6f) * w[tid];
    smv[tid] = qn;
    __syncthreads();
    const float rot = (tid < 64) ? -smv[tid+64] : smv[tid-64];
    const size_t ci = ((size_t)b*SS + s)*HD + tid;
    data[(size_t)row*HD + tid] = qn * cp[ci] + rot * sp[ci];
}

// ---------------------------------------------------------------------------
// Flash attention, fp32. Epilogue emits y as bf16 hi/lo pair.
// ---------------------------------------------------------------------------
__device__ __forceinline__ void store_pair4(__nv_bfloat16* hp, __nv_bfloat16* lp,
                                            float a, float b, float c, float d)
{
    uint32_t ba = __float_as_uint(a), bbt = __float_as_uint(b);
    uint32_t bc = __float_as_uint(c), bd = __float_as_uint(d);
    uint32_t h01 = __byte_perm(ba, bbt, 0x7632);
    uint32_t h23 = __byte_perm(bc, bd, 0x7632);
    float ra = a - __uint_as_float(ba & 0xffff0000u);
    float rb = b - __uint_as_float(bbt & 0xffff0000u);
    float rc = c - __uint_as_float(bc & 0xffff0000u);
    float rd = d - __uint_as_float(bd & 0xffff0000u);
    __nv_bfloat162 l01 = __float22bfloat162_rn(make_float2(ra, rb));
    __nv_bfloat162 l23 = __float22bfloat162_rn(make_float2(rc, rd));
    *(uint2*)hp = make_uint2(h01, h23);
    uint2 lw2;
    lw2.x = *(uint32_t*)&l01;
    lw2.y = *(uint32_t*)&l23;
    *(uint2*)lp = lw2;
}

#define PS 68
#define FLASH_SMEM ((128*64 + 128*64 + 64*128 + 64*PS + 192)*4)

__global__ __launch_bounds__(256)
void flash_kernel()
{
    extern __shared__ float sm[];
    float* Qs = sm;
    float* Ks = Qs + 128*64;
    float* Vs = Ks + 128*64;
    float* Psm = Vs + 64*128;
    float* Mr = Psm + 64*PS;
    float* Lr = Mr + 64;
    float* Ar = Lr + 64;

    const int tid = threadIdx.x;
    const int tx = tid & 15, ty = tid >> 4;
    const int qb = blockIdx.x;
    const int bh = blockIdx.y;
    const size_t base = (size_t)bh * SS * HD;
    const float* Qg = g_q + base + (size_t)qb * 64 * HD;
    const float* Kg = g_k + base;
    const float* Vg = g_v + base;

    {
        const int r = tid >> 2, c0 = (tid & 3) << 2;
        #pragma unroll
        for (int c = 0; c < 8; c++) {
            const int col = c0 + c*16;
            float4 v = *(const float4*)(Qg + (size_t)r*HD + col);
            Qs[(col+0)*64 + r] = v.x;
            Qs[(col+1)*64 + r] = v.y;
            Qs[(col+2)*64 + r] = v.z;
            Qs[(col+3)*64 + r] = v.w;
        }
    }
    if (tid < 64) { Mr[tid] = -1e30f; Lr[tid] = 0.f; }

    float O[4][8] = {};

    for (int kb = 0; kb < SS/64; kb++) {
        __syncthreads();
        {
            const int r = tid >> 2, c0 = (tid & 3) << 2;
            const float* kp = Kg + (size_t)(kb*64 + r)*HD;
            const float* vp = Vg + (size_t)(kb*64 + r)*HD;
            #pragma unroll
            for (int c = 0; c < 8; c++) {
                const int col = c0 + c*16;
                float4 kv = *(const float4*)(kp + col);
                Ks[(col+0)*64 + r] = kv.x;
                Ks[(col+1)*64 + r] = kv.y;
                Ks[(col+2)*64 + r] = kv.z;
                Ks[(col+3)*64 + r] = kv.w;
                *(float4*)(Vs + (size_t)r*HD + col) = *(const float4*)(vp + col);
            }
        }
        __syncthreads();

        float Sacc[4][4] = {};
        #pragma unroll 8
        for (int k = 0; k < HD; k++) {
            float a[4], b[4];
            *(float4*)a = *(const float4*)(Qs + k*64 + ty*4);
            *(float4*)b = *(const float4*)(Ks + k*64 + tx*4);
            #pragma unroll
            for (int i = 0; i < 4; i++)
                #pragma unroll
                for (int j = 0; j < 4; j++)
                    Sacc[i][j] += a[i]*b[j];
        }
        const float sc = 0.08838834764831845f;
        #pragma unroll
        for (int i = 0; i < 4; i++) {
            float4 v = make_float4(Sacc[i][0]*sc, Sacc[i][1]*sc,
                                   Sacc[i][2]*sc, Sacc[i][3]*sc);
            *(float4*)(Psm + (ty*4+i)*PS + tx*4) = v;
        }
        __syncthreads();

        if (tid < 64) {
            float* pr = Psm + tid*PS;
            const float mold = Mr[tid];
            float mx = mold;
            #pragma unroll 8
            for (int j = 0; j < 64; j++) mx = fmaxf(mx, pr[j]);
            const float alpha = __expf(mold - mx);
            float sum = 0.f;
            #pragma unroll 8
            for (int j = 0; j < 64; j++) {
                const float p = __expf(pr[j] - mx);
                pr[j] = p;
                sum += p;
            }
            Lr[tid] = Lr[tid]*alpha + sum;
            Mr[tid] = mx;
            Ar[tid] = alpha;
        }
        __syncthreads();

        float al[4];
        #pragma unroll
        for (int i = 0; i < 4; i++) al[i] = Ar[ty*4+i];
        #pragma unroll
        for (int i = 0; i < 4; i++)
            #pragma unroll
            for (int j = 0; j < 8; j++) O[i][j] *= al[i];

        #pragma unroll 2
        for (int j0 = 0; j0 < 64; j0 += 4) {
            float p[4][4];
            #pragma unroll
            for (int i = 0; i < 4; i++)
                *(float4*)p[i] = *(const float4*)(Psm + (ty*4+i)*PS + j0);
            #pragma unroll
            for (int jj = 0; jj < 4; jj++) {
                float vv[8];
                *(float4*)&vv[0] = *(const float4*)(Vs + (j0+jj)*HD + tx*4);
                *(float4*)&vv[4] = *(const float4*)(Vs + (j0+jj)*HD + 64 + tx*4);
                #pragma unroll
                for (int i = 0; i < 4; i++)
                    #pragma unroll
                    for (int c = 0; c < 8; c++)
                        O[i][c] += p[i][jj]*vv[c];
            }
        }
    }

    const int b = bh / HH, h = bh % HH;
    #pragma unroll
    for (int i = 0; i < 4; i++) {
        const int r = ty*4 + i;
        const float linv = 1.0f / Lr[r];
        const int s = qb*64 + r;
        const size_t yb = ((size_t)(b*SS + s)*HH + h)*HD;
        store_pair4(g_yhi + yb + tx*4, g_ylo + yb + tx*4,
                    O[i][0]*linv, O[i][1]*linv, O[i][2]*linv, O[i][3]*linv);
        store_pair4(g_yhi + yb + 64 + tx*4, g_ylo + yb + 64 + tx*4,
                    O[i][4]*linv, O[i][5]*linv, O[i][6]*linv, O[i][7]*linv);
    }
}

// ---------------------------------------------------------------------------
extern "C" void kernel_launch(void* const* d_in, const int* in_sizes, int n_in,
                              void* d_out, int out_size)
{
    const float* x   = (const float*)d_in[0];
    const float* ctx = (const float*)d_in[1];
    const float* cq  = (const float*)d_in[2];
    const float* sq  = (const float*)d_in[3];
    const float* ck  = (const float*)d_in[4];
    const float* sk  = (const float*)d_in[5];
    const float* Wq  = (const float*)d_in[6];
    const float* Wk  = (const float*)d_in[7];
    const float* Wv  = (const float*)d_in[8];
    const float* Wo  = (const float*)d_in[9];
    const float* qw  = (const float*)d_in[10];
    const float* kw  = (const float*)d_in[11];
    float* out = (float*)d_out;

    float *gq, *gk, *gv;
    __nv_bfloat16 *xh, *xl, *ch, *cl, *wqh, *wql, *wkh, *wkl, *wvh, *wvl, *woh, *wol, *yh, *yl;
    cudaGetSymbolAddress((void**)&gq, g_q);
    cudaGetSymbolAddress((void**)&gk, g_k);
    cudaGetSymbolAddress((void**)&gv, g_v);
    cudaGetSymbolAddress((void**)&xh, g_xhi);  cudaGetSymbolAddress((void**)&xl, g_xlo);
    cudaGetSymbolAddress((void**)&ch, g_chi);  cudaGetSymbolAddress((void**)&cl, g_clo);
    cudaGetSymbolAddress((void**)&wqh, g_wqh); cudaGetSymbolAddress((void**)&wql, g_wql);
    cudaGetSymbolAddress((void**)&wkh, g_wkh); cudaGetSymbolAddress((void**)&wkl, g_wkl);
    cudaGetSymbolAddress((void**)&wvh, g_wvh); cudaGetSymbolAddress((void**)&wvl, g_wvl);
    cudaGetSymbolAddress((void**)&woh, g_woh); cudaGetSymbolAddress((void**)&wol, g_wol);
    cudaGetSymbolAddress((void**)&yh, g_yhi);  cudaGetSymbolAddress((void**)&yl, g_ylo);

    cudaFuncSetAttribute(flash_kernel,
                         cudaFuncAttributeMaxDynamicSharedMemorySize, FLASH_SMEM);
    cudaFuncSetAttribute(gemm_mma<true>,
                         cudaFuncAttributeMaxDynamicSharedMemorySize, GEMM_DSMEM);
    cudaFuncSetAttribute(gemm_mma<false>,
                         cudaFuncAttributeMaxDynamicSharedMemorySize, GEMM_DSMEM);

    const int n4a = NROWS*DM/4;
    const int n4w = DM*DM/4;
    cvt_kernel<<<n4a/256, 256>>>(x,   xh, xl, n4a);
    cvt_kernel<<<n4a/256, 256>>>(ctx, ch, cl, n4a);
    cvt_kernel<<<n4w/256, 256>>>(Wq, wqh, wql, n4w);
    cvt_kernel<<<n4w/256, 256>>>(Wk, wkh, wkl, n4w);
    cvt_kernel<<<n4w/256, 256>>>(Wv, wvh, wvl, n4w);
    cvt_kernel<<<n4w/256, 256>>>(Wo, woh, wol, n4w);

    dim3 gg(DM/128, NROWS/128);     // (16, 32)
    gemm_mma<true><<<gg, 256, GEMM_DSMEM>>>(xh, xl, wqh, wql, gq);
    gemm_mma<true><<<gg, 256, GEMM_DSMEM>>>(ch, cl, wkh, wkl, gk);
    gemm_mma<true><<<gg, 256, GEMM_DSMEM>>>(ch, cl, wvh, wvl, gv);
    rms_rope_kernel<<<dim3(BB*HH*SS, 2), HD>>>(cq, sq, ck, sk, qw, kw);
    flash_kernel<<<dim3(SS/64, BB*HH), 256, FLASH_SMEM>>>();
    gemm_mma<false><<<gg, 256, GEMM_DSMEM>>>(yh, yl, woh, wol, out);
}

// round 5
// speedup vs baseline: 2.8527x; 1.9185x over previous
#include <cuda_runtime.h>
#include <cuda_bf16.h>
#include <cstdint>

#define BB 2
#define SS 2048
#define DM 2048
#define HH 16
#define HD 128
#define NROWS (BB*SS)

// ---------------------------------------------------------------------------
// Helpers (plain sm_80-era PTX only: ldmatrix / mma.sync / cp.async)
// ---------------------------------------------------------------------------
__device__ __forceinline__ uint32_t smem_to_u32(const void* p) {
    uint32_t a;
    asm("{ .reg .u64 t; cvta.to.shared.u64 t, %1; cvt.u32.u64 %0, t; }" : "=r"(a) : "l"(p));
    return a;
}
#define SWZ128(off) ((off) ^ (((off) >> 3) & 0x70))
#define SWZ256(off) ((off) ^ ((((off) >> 8) & 7) << 4))

__device__ __forceinline__ void cpa16(uint32_t s, const void* g) {
    asm volatile("cp.async.cg.shared.global [%0], [%1], 16;" :: "r"(s), "l"(g));
}
#define CP_COMMIT() asm volatile("cp.async.commit_group;" ::: "memory")
#define CP_WAIT1()  asm volatile("cp.async.wait_group 1;" ::: "memory")
#define CP_WAIT0()  asm volatile("cp.async.wait_group 0;" ::: "memory")

__device__ __forceinline__ void ldmx4(uint32_t& r0, uint32_t& r1, uint32_t& r2, uint32_t& r3,
                                      uint32_t addr) {
    asm volatile("ldmatrix.sync.aligned.m8n8.x4.shared.b16 {%0,%1,%2,%3}, [%4];"
                 : "=r"(r0), "=r"(r1), "=r"(r2), "=r"(r3) : "r"(addr));
}
__device__ __forceinline__ void ldmx4t(uint32_t& r0, uint32_t& r1, uint32_t& r2, uint32_t& r3,
                                       uint32_t addr) {
    asm volatile("ldmatrix.sync.aligned.m8n8.x4.trans.shared.b16 {%0,%1,%2,%3}, [%4];"
                 : "=r"(r0), "=r"(r1), "=r"(r2), "=r"(r3) : "r"(addr));
}
__device__ __forceinline__ void mma16816(float* c, const uint32_t* a, const uint32_t* b) {
    asm volatile("mma.sync.aligned.m16n8k16.row.col.f32.bf16.bf16.f32 "
                 "{%0,%1,%2,%3}, {%4,%5,%6,%7}, {%8,%9}, {%0,%1,%2,%3};"
                 : "+f"(c[0]), "+f"(c[1]), "+f"(c[2]), "+f"(c[3])
                 : "r"(a[0]), "r"(a[1]), "r"(a[2]), "r"(a[3]), "r"(b[0]), "r"(b[1]));
}

__device__ __forceinline__ uint32_t pack_rn(float a, float b) {
    __nv_bfloat162 t = __float22bfloat162_rn(make_float2(a, b));
    return *(uint32_t*)&t;
}
__device__ __forceinline__ uint32_t pack_hi(float a, float b) {
    return __byte_perm(__float_as_uint(a), __float_as_uint(b), 0x7632);
}
__device__ __forceinline__ uint32_t pack_lo(float a, float b) {
    float ra = a - __uint_as_float(__float_as_uint(a) & 0xffff0000u);
    float rb = b - __uint_as_float(__float_as_uint(b) & 0xffff0000u);
    return pack_rn(ra, rb);
}

// ---------------------------------------------------------------------------
// Device scratch
// ---------------------------------------------------------------------------
__device__ __align__(256) float g_q[(size_t)BB*HH*SS*HD];
__device__ __align__(256) float g_k[(size_t)BB*HH*SS*HD];
__device__ __align__(256) __nv_bfloat16 g_xhi[(size_t)NROWS*DM];
__device__ __align__(256) __nv_bfloat16 g_xlo[(size_t)NROWS*DM];
__device__ __align__(256) __nv_bfloat16 g_chi[(size_t)NROWS*DM];
__device__ __align__(256) __nv_bfloat16 g_clo[(size_t)NROWS*DM];
__device__ __align__(256) __nv_bfloat16 g_wqh[DM*DM], g_wql[DM*DM];
__device__ __align__(256) __nv_bfloat16 g_wkh[DM*DM], g_wkl[DM*DM];
__device__ __align__(256) __nv_bfloat16 g_wvh[DM*DM], g_wvl[DM*DM];
__device__ __align__(256) __nv_bfloat16 g_woh[DM*DM], g_wol[DM*DM];
__device__ __align__(256) __nv_bfloat16 g_qhi[(size_t)BB*HH*SS*HD], g_qlo[(size_t)BB*HH*SS*HD];
__device__ __align__(256) __nv_bfloat16 g_khi[(size_t)BB*HH*SS*HD], g_klo[(size_t)BB*HH*SS*HD];
__device__ __align__(256) __nv_bfloat16 g_vhi[(size_t)BB*HH*SS*HD], g_vlo[(size_t)BB*HH*SS*HD];
__device__ __align__(256) __nv_bfloat16 g_yhi[(size_t)NROWS*DM];
__device__ __align__(256) __nv_bfloat16 g_ylo[(size_t)NROWS*DM];

// ---------------------------------------------------------------------------
// fp32 -> (hi = truncated bf16 [exact], lo = RN bf16 of residual)
// ---------------------------------------------------------------------------
__global__ void cvt_kernel(const float* __restrict__ src, __nv_bfloat16* __restrict__ hi,
                           __nv_bfloat16* __restrict__ lo, int n4)
{
    int i = blockIdx.x*blockDim.x + threadIdx.x;
    if (i >= n4) return;
    float4 v = ((const float4*)src)[i];
    uint2 h = make_uint2(pack_hi(v.x, v.y), pack_hi(v.z, v.w));
    uint2 l = make_uint2(pack_lo(v.x, v.y), pack_lo(v.z, v.w));
    ((uint2*)hi)[i] = h;
    ((uint2*)lo)[i] = l;
}

// ---------------------------------------------------------------------------
// mma.sync bf16-pair GEMM: C[m,n] = sum_k A[m,k]*W[n,k]
// MODE 0: plain fp32 C.  MODE 1: HEADOUT fp32 (B,H,S,hd).  MODE 2: HEADOUT
// bf16 hi/lo pair (for V).
// ---------------------------------------------------------------------------
#define KC 64
#define NSTG (DM/KC)
#define AH_OFF 0
#define AL_OFF 16384
#define BH_OFF 32768
#define BL_OFF 49152
#define STG_BYTES 65536
#define GEMM_DSMEM (2*STG_BYTES + 1024)

template<int MODE>
__global__ __launch_bounds__(256, 1)
void gemm_mma(const __nv_bfloat16* __restrict__ Ah, const __nv_bfloat16* __restrict__ Al,
              const __nv_bfloat16* __restrict__ Bh, const __nv_bfloat16* __restrict__ Bl,
              float* __restrict__ C, __nv_bfloat16* __restrict__ Ch,
              __nv_bfloat16* __restrict__ Cl)
{
    extern __shared__ char dsm_raw[];
    const uint32_t raw_u = smem_to_u32(dsm_raw);
    const uint32_t sbase = (raw_u + 1023u) & ~1023u;

    const int tid = threadIdx.x;
    const int wid = tid >> 5;
    const int lane = tid & 31;
    const int warp_m = wid >> 2;
    const int warp_n = wid & 3;
    const int m0 = blockIdx.y * 128;
    const int n0 = blockIdx.x * 128;

    const int prow = tid >> 1;
    const int phalf = tid & 1;
    const size_t gA = (size_t)(m0 + prow) * DM + phalf * 32;
    const size_t gB = (size_t)(n0 + prow) * DM + phalf * 32;

    float acc[4][4][4];
    #pragma unroll
    for (int i = 0; i < 4; i++)
        #pragma unroll
        for (int j = 0; j < 4; j++)
            #pragma unroll
            for (int r = 0; r < 4; r++) acc[i][j][r] = 0.f;

    {
        const uint32_t buf = sbase;
        #pragma unroll
        for (int c = 0; c < 4; c++) {
            const uint32_t sw = SWZ128((uint32_t)(prow*128 + (phalf*4 + c)*16));
            const size_t go = (size_t)c * 8;
            cpa16(buf + AH_OFF + sw, Ah + gA + go);
            cpa16(buf + AL_OFF + sw, Al + gA + go);
            cpa16(buf + BH_OFF + sw, Bh + gB + go);
            cpa16(buf + BL_OFF + sw, Bl + gB + go);
        }
        CP_COMMIT();
    }

    const int a_r = warp_m*64 + (lane & 15);
    const int a_cs = lane >> 4;
    const int b_r = warp_n*32 + ((lane >> 4) << 3) + (lane & 7);
    const int b_cs = (lane >> 3) & 1;

    for (int s = 0; s < NSTG; s++) {
        if (s + 1 < NSTG) {
            const uint32_t buf = sbase + ((s+1) & 1) * STG_BYTES;
            const size_t ko = (size_t)(s+1) * KC;
            #pragma unroll
            for (int c = 0; c < 4; c++) {
                const uint32_t sw = SWZ128((uint32_t)(prow*128 + (phalf*4 + c)*16));
                const size_t go = ko + (size_t)c * 8;
                cpa16(buf + AH_OFF + sw, Ah + gA + go);
                cpa16(buf + AL_OFF + sw, Al + gA + go);
                cpa16(buf + BH_OFF + sw, Bh + gB + go);
                cpa16(buf + BL_OFF + sw, Bl + gB + go);
            }
            CP_COMMIT();
            CP_WAIT1();
        } else {
            CP_WAIT0();
        }
        __syncthreads();

        const uint32_t buf = sbase + (s & 1) * STG_BYTES;
        #pragma unroll
        for (int ks = 0; ks < 4; ks++) {
            const int kc = ks * 2;
            uint32_t ah[4][4], al_[4][4], bh[4][2], bl[4][2];
            #pragma unroll
            for (int mt = 0; mt < 4; mt++) {
                const uint32_t off = (uint32_t)((a_r + mt*16)*128 + (kc + a_cs)*16);
                ldmx4(ah[mt][0], ah[mt][1], ah[mt][2], ah[mt][3], buf + AH_OFF + SWZ128(off));
                ldmx4(al_[mt][0], al_[mt][1], al_[mt][2], al_[mt][3], buf + AL_OFF + SWZ128(off));
            }
            #pragma unroll
            for (int np = 0; np < 2; np++) {
                const uint32_t off = (uint32_t)((b_r + np*16)*128 + (kc + b_cs)*16);
                ldmx4(bh[np*2][0], bh[np*2][1], bh[np*2+1][0], bh[np*2+1][1],
                      buf + BH_OFF + SWZ128(off));
                ldmx4(bl[np*2][0], bl[np*2][1], bl[np*2+1][0], bl[np*2+1][1],
                      buf + BL_OFF + SWZ128(off));
            }
            #pragma unroll
            for (int mt = 0; mt < 4; mt++)
                #pragma unroll
                for (int nt = 0; nt < 4; nt++) {
                    mma16816(acc[mt][nt], ah[mt], bh[nt]);
                    mma16816(acc[mt][nt], ah[mt], bl[nt]);
                    mma16816(acc[mt][nt], al_[mt], bh[nt]);
                }
        }
        __syncthreads();
    }

    #pragma unroll
    for (int mt = 0; mt < 4; mt++) {
        const int mrow = m0 + warp_m*64 + mt*16 + (lane >> 2);
        #pragma unroll
        for (int half = 0; half < 2; half++) {
            const int m = mrow + half*8;
            #pragma unroll
            for (int nt = 0; nt < 4; nt++) {
                const int nn = warp_n*32 + nt*8 + 2*(lane & 3);
                float vx = half ? acc[mt][nt][2] : acc[mt][nt][0];
                float vy = half ? acc[mt][nt][3] : acc[mt][nt][1];
                if (MODE == 0) {
                    *(float2*)(C + (size_t)m*DM + n0 + nn) = make_float2(vx, vy);
                } else {
                    const int b = m >> 11, sidx = m & (SS - 1);
                    const size_t off = ((size_t)((b*HH + blockIdx.x)*SS + sidx))*HD + nn;
                    if (MODE == 1) {
                        *(float2*)(C + off) = make_float2(vx, vy);
                    } else {
                        *(uint32_t*)(Ch + off) = pack_hi(vx, vy);
                        *(uint32_t*)(Cl + off) = pack_lo(vx, vy);
                    }
                }
            }
        }
    }
}

// ---------------------------------------------------------------------------
// RMS norm + RoPE; emits bf16 hi/lo pairs for the mma flash kernel.
// ---------------------------------------------------------------------------
__global__ void rms_rope_kernel(const float* __restrict__ cq, const float* __restrict__ sq,
                                const float* __restrict__ ck, const float* __restrict__ sk,
                                const float* __restrict__ qw, const float* __restrict__ kw)
{
    const int row = blockIdx.x;
    const int isk = blockIdx.y;
    const float* data = isk ? g_k : g_q;
    const float* cp = isk ? ck : cq;
    const float* sp = isk ? sk : sq;
    const float* w  = isk ? kw : qw;
    __nv_bfloat16* oh = isk ? g_khi : g_qhi;
    __nv_bfloat16* ol = isk ? g_klo : g_qlo;
    const int tid = threadIdx.x;
    const int s = row % SS;
    const int b = row / (HH*SS);

    __shared__ float smv[HD];
    __shared__ float red[4];
    float v = data[(size_t)row*HD + tid];
    float s2 = v*v;
    #pragma unroll
    for (int o = 16; o; o >>= 1) s2 += __shfl_xor_sync(0xffffffffu, s2, o);
    if ((tid & 31) == 0) red[tid >> 5] = s2;
    __syncthreads();
    const float var = (red[0]+red[1]+red[2]+red[3]) * (1.0f/HD);
    const float qn = v * rsqrtf(var + 1e-6f) * w[tid];
    smv[tid] = qn;
    __syncthreads();
    const float rot = (tid < 64) ? -smv[tid+64] : smv[tid-64];
    const size_t ci = ((size_t)b*SS + s)*HD + tid;
    const float val = qn * cp[ci] + rot * sp[ci];
    const uint32_t bits = __float_as_uint(val);
    const float hi = __uint_as_float(bits & 0xffff0000u);
    oh[(size_t)row*HD + tid] = __ushort_as_bfloat16((unsigned short)(bits >> 16));
    ol[(size_t)row*HD + tid] = __float2bfloat16_rn(val - hi);
}

// ---------------------------------------------------------------------------
// Flash attention on mma.sync. CTA = 128 queries, 8 warps x 16 rows.
// Q hi/lo resident in smem; K/V hi/lo double-buffered via cp.async.
// S = 3-product hi/lo; P hi/lo x V hi/lo (3-product; Pl*Vl dropped).
// ---------------------------------------------------------------------------
#define FB_QH 0
#define FB_QL 32768
#define FB_ST 65536
#define ST_SZ 65536
#define T_KH 0
#define T_KL 16384
#define T_VH 32768
#define T_VL 49152
#define NKB (SS/64)
#define FLASH_DSMEM (FB_ST + 2*ST_SZ + 1024)

__global__ __launch_bounds__(256, 1)
void flash_mma()
{
    extern __shared__ char fsm_raw[];
    const uint32_t raw_u = smem_to_u32(fsm_raw);
    const uint32_t sb0 = (raw_u + 1023u) & ~1023u;
    char* bp = fsm_raw + (sb0 - raw_u);

    const int tid = threadIdx.x;
    const int wid = tid >> 5;
    const int lane = tid & 31;
    const int qb = blockIdx.x;
    const int bh = blockIdx.y;

    const size_t base = (size_t)bh * SS * HD;
    const char* Qh = (const char*)(g_qhi + base + (size_t)qb * 128 * HD);
    const char* Ql = (const char*)(g_qlo + base + (size_t)qb * 128 * HD);
    const char* Kh = (const char*)(g_khi + base);
    const char* Kl = (const char*)(g_klo + base);
    const char* Vh = (const char*)(g_vhi + base);
    const char* Vl = (const char*)(g_vlo + base);

    // Q -> smem (one-time, 64 KB)
    #pragma unroll
    for (int i = 0; i < 8; i++) {
        const int idx = tid + i*256;           // 0..2047
        const int row = idx >> 4, c = idx & 15;
        const uint32_t d = SWZ256((uint32_t)(row*256 + c*16));
        *(uint4*)(bp + FB_QH + d) = *(const uint4*)(Qh + (size_t)row*256 + c*16);
        *(uint4*)(bp + FB_QL + d) = *(const uint4*)(Ql + (size_t)row*256 + c*16);
    }

    // prefetch stage 0
    {
        const uint32_t sb = sb0 + FB_ST;
        #pragma unroll
        for (int j = 0; j < 4; j++) {
            const int idx = tid + j*256;       // 0..1023
            const int row = idx >> 4, c = idx & 15;
            const uint32_t d = SWZ256((uint32_t)(row*256 + c*16));
            const size_t go = (size_t)row*256 + c*16;
            cpa16(sb + T_KH + d, Kh + go);
            cpa16(sb + T_KL + d, Kl + go);
            cpa16(sb + T_VH + d, Vh + go);
            cpa16(sb + T_VL + d, Vl + go);
        }
        CP_COMMIT();
    }

    float sacc[8][4];
    float oacc[16][4];
    #pragma unroll
    for (int i = 0; i < 16; i++)
        #pragma unroll
        for (int r = 0; r < 4; r++) oacc[i][r] = 0.f;
    float m0 = -1e30f, m1 = -1e30f, l0 = 0.f, l1 = 0.f;

    const int w16 = wid * 16;
    const uint32_t qa_off = (uint32_t)((w16 + (lane & 15))*256 + (lane >> 4)*16);
    const uint32_t kb_row = (uint32_t)(((lane >> 4) << 3) + (lane & 7));
    const uint32_t kb_cs = (uint32_t)(((lane >> 3) & 1) * 16);
    const uint32_t vb_row = (uint32_t)((lane & 7) + (((lane >> 3) & 1) << 3));
    const uint32_t vb_cs = (uint32_t)((lane >> 4) * 16);
    const float sc = 0.08838834764831845f;

    for (int kb = 0; kb < NKB; kb++) {
        if (kb > 0) __syncthreads();
        if (kb + 1 < NKB) {
            const uint32_t sb = sb0 + FB_ST + ((kb+1) & 1) * ST_SZ;
            const size_t kbase = (size_t)(kb+1) * 64 * 256;
            #pragma unroll
            for (int j = 0; j < 4; j++) {
                const int idx = tid + j*256;
                const int row = idx >> 4, c = idx & 15;
                const uint32_t d = SWZ256((uint32_t)(row*256 + c*16));
                const size_t go = kbase + (size_t)row*256 + c*16;
                cpa16(sb + T_KH + d, Kh + go);
                cpa16(sb + T_KL + d, Kl + go);
                cpa16(sb + T_VH + d, Vh + go);
                cpa16(sb + T_VL + d, Vl + go);
            }
            CP_COMMIT();
            CP_WAIT1();
        } else {
            CP_WAIT0();
        }
        __syncthreads();

        const uint32_t sb = sb0 + FB_ST + (kb & 1) * ST_SZ;

        // ---- S = Q K^T (3-product)
        #pragma unroll
        for (int i = 0; i < 8; i++)
            #pragma unroll
            for (int r = 0; r < 4; r++) sacc[i][r] = 0.f;

        #pragma unroll
        for (int kk = 0; kk < 8; kk++) {
            uint32_t qh4[4], ql4[4];
            const uint32_t qa = sb0 + FB_QH + SWZ256(qa_off + (uint32_t)kk*32);
            ldmx4(qh4[0], qh4[1], qh4[2], qh4[3], qa);
            ldmx4(ql4[0], ql4[1], ql4[2], ql4[3], qa + (FB_QL - FB_QH));
            #pragma unroll
            for (int n16 = 0; n16 < 4; n16++) {
                uint32_t kh4[4], kl4[4];
                const uint32_t ka = sb + T_KH +
                    SWZ256((uint32_t)((n16*16 + kb_row)*256 + kk*32 + kb_cs));
                ldmx4(kh4[0], kh4[1], kh4[2], kh4[3], ka);
                ldmx4(kl4[0], kl4[1], kl4[2], kl4[3], ka + (T_KL - T_KH));
                mma16816(sacc[2*n16],   qh4, &kh4[0]);
                mma16816(sacc[2*n16],   qh4, &kl4[0]);
                mma16816(sacc[2*n16],   ql4, &kh4[0]);
                mma16816(sacc[2*n16+1], qh4, &kh4[2]);
                mma16816(sacc[2*n16+1], qh4, &kl4[2]);
                mma16816(sacc[2*n16+1], ql4, &kh4[2]);
            }
        }

        // ---- online softmax (warp-local; rows g = lane>>2 and g+8)
        #pragma unroll
        for (int i = 0; i < 8; i++)
            #pragma unroll
            for (int r = 0; r < 4; r++) sacc[i][r] *= sc;

        float nm0 = -1e30f, nm1 = -1e30f;
        #pragma unroll
        for (int i = 0; i < 8; i++) {
            nm0 = fmaxf(nm0, fmaxf(sacc[i][0], sacc[i][1]));
            nm1 = fmaxf(nm1, fmaxf(sacc[i][2], sacc[i][3]));
        }
        nm0 = fmaxf(nm0, __shfl_xor_sync(0xffffffffu, nm0, 1));
        nm0 = fmaxf(nm0, __shfl_xor_sync(0xffffffffu, nm0, 2));
        nm1 = fmaxf(nm1, __shfl_xor_sync(0xffffffffu, nm1, 1));
        nm1 = fmaxf(nm1, __shfl_xor_sync(0xffffffffu, nm1, 2));
        const float mn0 = fmaxf(m0, nm0), mn1 = fmaxf(m1, nm1);
        const float a0 = __expf(m0 - mn0), a1 = __expf(m1 - mn1);
        m0 = mn0; m1 = mn1;
        float ls0 = 0.f, ls1 = 0.f;
        #pragma unroll
        for (int i = 0; i < 8; i++) {
            float p0 = __expf(sacc[i][0] - m0); sacc[i][0] = p0; ls0 += p0;
            float p1 = __expf(sacc[i][1] - m0); sacc[i][1] = p1; ls0 += p1;
            float p2 = __expf(sacc[i][2] - m1); sacc[i][2] = p2; ls1 += p2;
            float p3 = __expf(sacc[i][3] - m1); sacc[i][3] = p3; ls1 += p3;
        }
        ls0 += __shfl_xor_sync(0xffffffffu, ls0, 1);
        ls0 += __shfl_xor_sync(0xffffffffu, ls0, 2);
        ls1 += __shfl_xor_sync(0xffffffffu, ls1, 1);
        ls1 += __shfl_xor_sync(0xffffffffu, ls1, 2);
        l0 = l0*a0 + ls0;
        l1 = l1*a1 + ls1;
        #pragma unroll
        for (int i = 0; i < 16; i++) {
            oacc[i][0] *= a0; oacc[i][1] *= a0;
            oacc[i][2] *= a1; oacc[i][3] *= a1;
        }

        // ---- O += P V  (P hi/lo x V hi/lo, 3-product)
        #pragma unroll
        for (int kk = 0; kk < 4; kk++) {
            uint32_t ph[4], pl[4];
            ph[0] = pack_hi(sacc[2*kk][0],   sacc[2*kk][1]);
            pl[0] = pack_lo(sacc[2*kk][0],   sacc[2*kk][1]);
            ph[1] = pack_hi(sacc[2*kk][2],   sacc[2*kk][3]);
            pl[1] = pack_lo(sacc[2*kk][2],   sacc[2*kk][3]);
            ph[2] = pack_hi(sacc[2*kk+1][0], sacc[2*kk+1][1]);
            pl[2] = pack_lo(sacc[2*kk+1][0], sacc[2*kk+1][1]);
            ph[3] = pack_hi(sacc[2*kk+1][2], sacc[2*kk+1][3]);
            pl[3] = pack_lo(sacc[2*kk+1][2], sacc[2*kk+1][3]);
            #pragma unroll
            for (int n16 = 0; n16 < 8; n16++) {
                uint32_t vh4[4], vl4[4];
                const uint32_t va = sb + T_VH +
                    SWZ256((uint32_t)((kk*16 + vb_row)*256 + n16*32 + vb_cs));
                ldmx4t(vh4[0], vh4[1], vh4[2], vh4[3], va);
                ldmx4t(vl4[0], vl4[1], vl4[2], vl4[3], va + (T_VL - T_VH));
                mma16816(oacc[2*n16],   ph, &vh4[0]);
                mma16816(oacc[2*n16],   pl, &vh4[0]);
                mma16816(oacc[2*n16],   ph, &vl4[0]);
                mma16816(oacc[2*n16+1], ph, &vh4[2]);
                mma16816(oacc[2*n16+1], pl, &vh4[2]);
                mma16816(oacc[2*n16+1], ph, &vl4[2]);
            }
        }
    }

    // ---- epilogue: y as bf16 hi/lo, (B, S, H, hd) layout
    const int b = bh / HH, h = bh % HH;
    const int g = lane >> 2;
    const int col0 = (lane & 3) * 2;
    const float li0 = 1.0f / l0, li1 = 1.0f / l1;
    const int s0 = qb*128 + w16 + g;
    const size_t yb0 = ((size_t)(b*SS + s0)*HH + h)*HD;
    const size_t yb1 = ((size_t)(b*SS + s0 + 8)*HH + h)*HD;
    #pragma unroll
    for (int nt = 0; nt < 16; nt++) {
        const int c = nt*8 + col0;
        const float x0 = oacc[nt][0]*li0, y0 = oacc[nt][1]*li0;
        const float x1 = oacc[nt][2]*li1, y1 = oacc[nt][3]*li1;
        *(uint32_t*)(g_yhi + yb0 + c) = pack_hi(x0, y0);
        *(uint32_t*)(g_ylo + yb0 + c) = pack_lo(x0, y0);
        *(uint32_t*)(g_yhi + yb1 + c) = pack_hi(x1, y1);
        *(uint32_t*)(g_ylo + yb1 + c) = pack_lo(x1, y1);
    }
}

// ---------------------------------------------------------------------------
extern "C" void kernel_launch(void* const* d_in, const int* in_sizes, int n_in,
                              void* d_out, int out_size)
{
    const float* x   = (const float*)d_in[0];
    const float* ctx = (const float*)d_in[1];
    const float* cq  = (const float*)d_in[2];
    const float* sq  = (const float*)d_in[3];
    const float* ck  = (const float*)d_in[4];
    const float* sk  = (const float*)d_in[5];
    const float* Wq  = (const float*)d_in[6];
    const float* Wk  = (const float*)d_in[7];
    const float* Wv  = (const float*)d_in[8];
    const float* Wo  = (const float*)d_in[9];
    const float* qw  = (const float*)d_in[10];
    const float* kw  = (const float*)d_in[11];
    float* out = (float*)d_out;

    float *gq, *gk;
    __nv_bfloat16 *xh, *xl, *ch, *cl, *wqh, *wql, *wkh, *wkl, *wvh, *wvl, *woh, *wol;
    __nv_bfloat16 *vh, *vl, *yh, *yl;
    cudaGetSymbolAddress((void**)&gq, g_q);
    cudaGetSymbolAddress((void**)&gk, g_k);
    cudaGetSymbolAddress((void**)&xh, g_xhi);  cudaGetSymbolAddress((void**)&xl, g_xlo);
    cudaGetSymbolAddress((void**)&ch, g_chi);  cudaGetSymbolAddress((void**)&cl, g_clo);
    cudaGetSymbolAddress((void**)&wqh, g_wqh); cudaGetSymbolAddress((void**)&wql, g_wql);
    cudaGetSymbolAddress((void**)&wkh, g_wkh); cudaGetSymbolAddress((void**)&wkl, g_wkl);
    cudaGetSymbolAddress((void**)&wvh, g_wvh); cudaGetSymbolAddress((void**)&wvl, g_wvl);
    cudaGetSymbolAddress((void**)&woh, g_woh); cudaGetSymbolAddress((void**)&wol, g_wol);
    cudaGetSymbolAddress((void**)&vh, g_vhi);  cudaGetSymbolAddress((void**)&vl, g_vlo);
    cudaGetSymbolAddress((void**)&yh, g_yhi);  cudaGetSymbolAddress((void**)&yl, g_ylo);

    cudaFuncSetAttribute(gemm_mma<0>, cudaFuncAttributeMaxDynamicSharedMemorySize, GEMM_DSMEM);
    cudaFuncSetAttribute(gemm_mma<1>, cudaFuncAttributeMaxDynamicSharedMemorySize, GEMM_DSMEM);
    cudaFuncSetAttribute(gemm_mma<2>, cudaFuncAttributeMaxDynamicSharedMemorySize, GEMM_DSMEM);
    cudaFuncSetAttribute(flash_mma,   cudaFuncAttributeMaxDynamicSharedMemorySize, FLASH_DSMEM);

    const int n4a = NROWS*DM/4;
    const int n4w = DM*DM/4;
    cvt_kernel<<<n4a/256, 256>>>(x,   xh, xl, n4a);
    cvt_kernel<<<n4a/256, 256>>>(ctx, ch, cl, n4a);
    cvt_kernel<<<n4w/256, 256>>>(Wq, wqh, wql, n4w);
    cvt_kernel<<<n4w/256, 256>>>(Wk, wkh, wkl, n4w);
    cvt_kernel<<<n4w/256, 256>>>(Wv, wvh, wvl, n4w);
    cvt_kernel<<<n4w/256, 256>>>(Wo, woh, wol, n4w);

    dim3 gg(DM/128, NROWS/128);     // (16, 32)
    gemm_mma<1><<<gg, 256, GEMM_DSMEM>>>(xh, xl, wqh, wql, gq, nullptr, nullptr);
    gemm_mma<1><<<gg, 256, GEMM_DSMEM>>>(ch, cl, wkh, wkl, gk, nullptr, nullptr);
    gemm_mma<2><<<gg, 256, GEMM_DSMEM>>>(ch, cl, wvh, wvl, nullptr, vh, vl);
    rms_rope_kernel<<<dim3(BB*HH*SS, 2), HD>>>(cq, sq, ck, sk, qw, kw);
    flash_mma<<<dim3(SS/128, BB*HH), 256, FLASH_DSMEM>>>();
    gemm_mma<0><<<gg, 256, GEMM_DSMEM>>>(yh, yl, woh, wol, out, nullptr, nullptr);
}

// round 6
// speedup vs baseline: 3.0243x; 1.0602x over previous
#include <cuda_runtime.h>
#include <cuda_bf16.h>
#include <cstdint>

#define BB 2
#define SS 2048
#define DM 2048
#define HH 16
#define HD 128
#define NROWS (BB*SS)

// ---------------------------------------------------------------------------
// Helpers (plain sm_80-era PTX only: ldmatrix / mma.sync / cp.async)
// ---------------------------------------------------------------------------
__device__ __forceinline__ uint32_t smem_to_u32(const void* p) {
    uint32_t a;
    asm("{ .reg .u64 t; cvta.to.shared.u64 t, %1; cvt.u32.u64 %0, t; }" : "=r"(a) : "l"(p));
    return a;
}
#define SWZ128(off) ((off) ^ (((off) >> 3) & 0x70))
#define SWZ256(off) ((off) ^ ((((off) >> 8) & 7) << 4))

__device__ __forceinline__ void cpa16(uint32_t s, const void* g) {
    asm volatile("cp.async.cg.shared.global [%0], [%1], 16;" :: "r"(s), "l"(g));
}
#define CP_COMMIT() asm volatile("cp.async.commit_group;" ::: "memory")
#define CP_WAIT1()  asm volatile("cp.async.wait_group 1;" ::: "memory")
#define CP_WAIT0()  asm volatile("cp.async.wait_group 0;" ::: "memory")

__device__ __forceinline__ void ldmx4(uint32_t& r0, uint32_t& r1, uint32_t& r2, uint32_t& r3,
                                      uint32_t addr) {
    asm volatile("ldmatrix.sync.aligned.m8n8.x4.shared.b16 {%0,%1,%2,%3}, [%4];"
                 : "=r"(r0), "=r"(r1), "=r"(r2), "=r"(r3) : "r"(addr));
}
__device__ __forceinline__ void ldmx4t(uint32_t& r0, uint32_t& r1, uint32_t& r2, uint32_t& r3,
                                       uint32_t addr) {
    asm volatile("ldmatrix.sync.aligned.m8n8.x4.trans.shared.b16 {%0,%1,%2,%3}, [%4];"
                 : "=r"(r0), "=r"(r1), "=r"(r2), "=r"(r3) : "r"(addr));
}
__device__ __forceinline__ void mma16816(float* c, const uint32_t* a, const uint32_t* b) {
    asm volatile("mma.sync.aligned.m16n8k16.row.col.f32.bf16.bf16.f32 "
                 "{%0,%1,%2,%3}, {%4,%5,%6,%7}, {%8,%9}, {%0,%1,%2,%3};"
                 : "+f"(c[0]), "+f"(c[1]), "+f"(c[2]), "+f"(c[3])
                 : "r"(a[0]), "r"(a[1]), "r"(a[2]), "r"(a[3]), "r"(b[0]), "r"(b[1]));
}

__device__ __forceinline__ uint32_t pack_rn(float a, float b) {
    __nv_bfloat162 t = __float22bfloat162_rn(make_float2(a, b));
    return *(uint32_t*)&t;
}
__device__ __forceinline__ uint32_t pack_hi(float a, float b) {
    return __byte_perm(__float_as_uint(a), __float_as_uint(b), 0x7632);
}
__device__ __forceinline__ uint32_t pack_lo(float a, float b) {
    float ra = a - __uint_as_float(__float_as_uint(a) & 0xffff0000u);
    float rb = b - __uint_as_float(__float_as_uint(b) & 0xffff0000u);
    return pack_rn(ra, rb);
}

// ---------------------------------------------------------------------------
// Device scratch
// ---------------------------------------------------------------------------
__device__ __align__(256) float g_q[(size_t)BB*HH*SS*HD];
__device__ __align__(256) float g_k[(size_t)BB*HH*SS*HD];
__device__ __align__(256) __nv_bfloat16 g_xhi[(size_t)NROWS*DM];
__device__ __align__(256) __nv_bfloat16 g_xlo[(size_t)NROWS*DM];
__device__ __align__(256) __nv_bfloat16 g_chi[(size_t)NROWS*DM];
__device__ __align__(256) __nv_bfloat16 g_clo[(size_t)NROWS*DM];
__device__ __align__(256) __nv_bfloat16 g_wqh[DM*DM], g_wql[DM*DM];
__device__ __align__(256) __nv_bfloat16 g_wkh[DM*DM], g_wkl[DM*DM];
__device__ __align__(256) __nv_bfloat16 g_wvh[DM*DM], g_wvl[DM*DM];
__device__ __align__(256) __nv_bfloat16 g_woh[DM*DM], g_wol[DM*DM];
__device__ __align__(256) __nv_bfloat16 g_qhi[(size_t)BB*HH*SS*HD], g_qlo[(size_t)BB*HH*SS*HD];
__device__ __align__(256) __nv_bfloat16 g_khi[(size_t)BB*HH*SS*HD], g_klo[(size_t)BB*HH*SS*HD];
__device__ __align__(256) __nv_bfloat16 g_vhi[(size_t)BB*HH*SS*HD], g_vlo[(size_t)BB*HH*SS*HD];
__device__ __align__(256) __nv_bfloat16 g_yhi[(size_t)NROWS*DM];
__device__ __align__(256) __nv_bfloat16 g_ylo[(size_t)NROWS*DM];

// ---------------------------------------------------------------------------
// Fused fp32 -> bf16 hi/lo conversion for all 6 tensors (segmented grid).
// Segments (in 256-thread blocks of 4 float4s): x:8192, ctx:8192, W*:4096 ea.
// ---------------------------------------------------------------------------
__global__ void cvt6_kernel(const float* __restrict__ x, const float* __restrict__ ctx,
                            const float* __restrict__ Wq, const float* __restrict__ Wk,
                            const float* __restrict__ Wv, const float* __restrict__ Wo)
{
    int bid = blockIdx.x;
    const float* src;
    __nv_bfloat16 *hi, *lo;
    int lb;
    if (bid < 8192)       { src = x;   hi = g_xhi; lo = g_xlo; lb = bid; }
    else if (bid < 16384) { src = ctx; hi = g_chi; lo = g_clo; lb = bid - 8192; }
    else if (bid < 20480) { src = Wq;  hi = g_wqh; lo = g_wql; lb = bid - 16384; }
    else if (bid < 24576) { src = Wk;  hi = g_wkh; lo = g_wkl; lb = bid - 20480; }
    else if (bid < 28672) { src = Wv;  hi = g_wvh; lo = g_wvl; lb = bid - 24576; }
    else                  { src = Wo;  hi = g_woh; lo = g_wol; lb = bid - 28672; }
    const int i = lb*256 + threadIdx.x;
    float4 v = ((const float4*)src)[i];
    ((uint2*)hi)[i] = make_uint2(pack_hi(v.x, v.y), pack_hi(v.z, v.w));
    ((uint2*)lo)[i] = make_uint2(pack_lo(v.x, v.y), pack_lo(v.z, v.w));
}

// ---------------------------------------------------------------------------
// 3-stage bf16-pair GEMM mainloop (shared by qkv_kernel and wo_kernel).
// CTA 128x128, KC=64, 8 warps (2m x 4n), 3 HMMA products per tile.
// ---------------------------------------------------------------------------
#define KC 64
#define NSTG (DM/KC)
#define AH_OFF 0
#define AL_OFF 16384
#define BH_OFF 32768
#define BL_OFF 49152
#define STG_BYTES 65536
#define GEMM_DSMEM (3*STG_BYTES + 1024)

__device__ __forceinline__ void gemm_body(
    const __nv_bfloat16* __restrict__ Ah, const __nv_bfloat16* __restrict__ Al,
    const __nv_bfloat16* __restrict__ Bh, const __nv_bfloat16* __restrict__ Bl,
    uint32_t sbase, char* sbase_p, int m0, int n0, float acc[4][4][4])
{
    const int tid = threadIdx.x;
    const int wid = tid >> 5;
    const int lane = tid & 31;
    const int warp_m = wid >> 2;
    const int warp_n = wid & 3;

    const int prow = tid >> 1;
    const int phalf = tid & 1;
    const size_t gA = (size_t)(m0 + prow) * DM + phalf * 32;
    const size_t gB = (size_t)(n0 + prow) * DM + phalf * 32;
    const uint32_t swp[4] = {
        SWZ128((uint32_t)(prow*128 + (phalf*4 + 0)*16)),
        SWZ128((uint32_t)(prow*128 + (phalf*4 + 1)*16)),
        SWZ128((uint32_t)(prow*128 + (phalf*4 + 2)*16)),
        SWZ128((uint32_t)(prow*128 + (phalf*4 + 3)*16)) };

    // prologue: prefetch stages 0, 1
    #pragma unroll
    for (int s = 0; s < 2; s++) {
        const uint32_t buf = sbase + s * STG_BYTES;
        const size_t ko = (size_t)s * KC;
        #pragma unroll
        for (int c = 0; c < 4; c++) {
            const size_t go = ko + (size_t)c * 8;
            cpa16(buf + AH_OFF + swp[c], Ah + gA + go);
            cpa16(buf + AL_OFF + swp[c], Al + gA + go);
            cpa16(buf + BH_OFF + swp[c], Bh + gB + go);
            cpa16(buf + BL_OFF + swp[c], Bl + gB + go);
        }
        CP_COMMIT();
    }

    const int a_r = warp_m*64 + (lane & 15);
    const int a_cs = lane >> 4;
    const int b_r = warp_n*32 + ((lane >> 4) << 3) + (lane & 7);
    const int b_cs = (lane >> 3) & 1;

    int sbuf = 0;          // buffer index of stage s
    for (int s = 0; s < NSTG; s++) {
        CP_WAIT1();        // stage s complete ({s+1} may remain in flight)
        __syncthreads();   // everyone done reading the buffer we're about to refill
        if (s + 2 < NSTG) {
            const int wbuf = (sbuf + 2 >= 3) ? (sbuf - 1) : (sbuf + 2);
            const uint32_t buf = sbase + wbuf * STG_BYTES;
            const size_t ko = (size_t)(s+2) * KC;
            #pragma unroll
            for (int c = 0; c < 4; c++) {
                const size_t go = ko + (size_t)c * 8;
                cpa16(buf + AH_OFF + swp[c], Ah + gA + go);
                cpa16(buf + AL_OFF + swp[c], Al + gA + go);
                cpa16(buf + BH_OFF + swp[c], Bh + gB + go);
                cpa16(buf + BL_OFF + swp[c], Bl + gB + go);
            }
            CP_COMMIT();
        }

        const uint32_t buf = sbase + sbuf * STG_BYTES;
        #pragma unroll
        for (int ks = 0; ks < 4; ks++) {
            const int kc = ks * 2;
            uint32_t ah[4][4], al_[4][4], bh[4][2], bl[4][2];
            #pragma unroll
            for (int mt = 0; mt < 4; mt++) {
                const uint32_t off = (uint32_t)((a_r + mt*16)*128 + (kc + a_cs)*16);
                ldmx4(ah[mt][0], ah[mt][1], ah[mt][2], ah[mt][3], buf + AH_OFF + SWZ128(off));
                ldmx4(al_[mt][0], al_[mt][1], al_[mt][2], al_[mt][3], buf + AL_OFF + SWZ128(off));
            }
            #pragma unroll
            for (int np = 0; np < 2; np++) {
                const uint32_t off = (uint32_t)((b_r + np*16)*128 + (kc + b_cs)*16);
                ldmx4(bh[np*2][0], bh[np*2][1], bh[np*2+1][0], bh[np*2+1][1],
                      buf + BH_OFF + SWZ128(off));
                ldmx4(bl[np*2][0], bl[np*2][1], bl[np*2+1][0], bl[np*2+1][1],
                      buf + BL_OFF + SWZ128(off));
            }
            #pragma unroll
            for (int mt = 0; mt < 4; mt++)
                #pragma unroll
                for (int nt = 0; nt < 4; nt++) {
                    mma16816(acc[mt][nt], ah[mt], bh[nt]);
                    mma16816(acc[mt][nt], ah[mt], bl[nt]);
                    mma16816(acc[mt][nt], al_[mt], bh[nt]);
                }
        }
        sbuf = (sbuf + 1 >= 3) ? 0 : (sbuf + 1);
    }
}

// ---------------------------------------------------------------------------
// Fused Q/K/V projection: blockIdx.z selects operand set + epilogue.
// z=0: Q = x @ Wq^T -> g_q fp32 HEADOUT
// z=1: K = ctx @ Wk^T -> g_k fp32 HEADOUT
// z=2: V = ctx @ Wv^T -> g_vhi/g_vlo HEADOUT
// ---------------------------------------------------------------------------
__global__ __launch_bounds__(256, 1)
void qkv_kernel()
{
    extern __shared__ char dsm_raw[];
    const uint32_t raw_u = smem_to_u32(dsm_raw);
    const uint32_t sbase = (raw_u + 1023u) & ~1023u;

    const int z = blockIdx.z;
    const __nv_bfloat16 *Ah, *Al, *Bh, *Bl;
    if (z == 0)      { Ah = g_xhi; Al = g_xlo; Bh = g_wqh; Bl = g_wql; }
    else if (z == 1) { Ah = g_chi; Al = g_clo; Bh = g_wkh; Bl = g_wkl; }
    else             { Ah = g_chi; Al = g_clo; Bh = g_wvh; Bl = g_wvl; }

    const int m0 = blockIdx.y * 128;
    const int n0 = blockIdx.x * 128;

    float acc[4][4][4];
    #pragma unroll
    for (int i = 0; i < 4; i++)
        #pragma unroll
        for (int j = 0; j < 4; j++)
            #pragma unroll
            for (int r = 0; r < 4; r++) acc[i][j][r] = 0.f;

    gemm_body(Ah, Al, Bh, Bl, sbase, dsm_raw, m0, n0, acc);

    const int tid = threadIdx.x;
    const int wid = tid >> 5;
    const int lane = tid & 31;
    const int warp_m = wid >> 2;
    const int warp_n = wid & 3;

    #pragma unroll
    for (int mt = 0; mt < 4; mt++) {
        const int mrow = m0 + warp_m*64 + mt*16 + (lane >> 2);
        #pragma unroll
        for (int half = 0; half < 2; half++) {
            const int m = mrow + half*8;
            const int b = m >> 11, sidx = m & (SS - 1);
            const size_t rb = ((size_t)((b*HH + blockIdx.x)*SS + sidx))*HD;
            #pragma unroll
            for (int nt = 0; nt < 4; nt++) {
                const int nn = warp_n*32 + nt*8 + 2*(lane & 3);
                float vx = half ? acc[mt][nt][2] : acc[mt][nt][0];
                float vy = half ? acc[mt][nt][3] : acc[mt][nt][1];
                if (z == 0) {
                    *(float2*)(g_q + rb + nn) = make_float2(vx, vy);
                } else if (z == 1) {
                    *(float2*)(g_k + rb + nn) = make_float2(vx, vy);
                } else {
                    *(uint32_t*)(g_vhi + rb + nn) = pack_hi(vx, vy);
                    *(uint32_t*)(g_vlo + rb + nn) = pack_lo(vx, vy);
                }
            }
        }
    }
}

// ---------------------------------------------------------------------------
// Output projection: out = y @ Wo^T, fp32 result.
// ---------------------------------------------------------------------------
__global__ __launch_bounds__(256, 1)
void wo_kernel(float* __restrict__ C)
{
    extern __shared__ char dsm_raw[];
    const uint32_t raw_u = smem_to_u32(dsm_raw);
    const uint32_t sbase = (raw_u + 1023u) & ~1023u;

    const int m0 = blockIdx.y * 128;
    const int n0 = blockIdx.x * 128;

    float acc[4][4][4];
    #pragma unroll
    for (int i = 0; i < 4; i++)
        #pragma unroll
        for (int j = 0; j < 4; j++)
            #pragma unroll
            for (int r = 0; r < 4; r++) acc[i][j][r] = 0.f;

    gemm_body(g_yhi, g_ylo, g_woh, g_wol, sbase, dsm_raw, m0, n0, acc);

    const int tid = threadIdx.x;
    const int wid = tid >> 5;
    const int lane = tid & 31;
    const int warp_m = wid >> 2;
    const int warp_n = wid & 3;

    #pragma unroll
    for (int mt = 0; mt < 4; mt++) {
        const int mrow = m0 + warp_m*64 + mt*16 + (lane >> 2);
        #pragma unroll
        for (int half = 0; half < 2; half++) {
            const int m = mrow + half*8;
            #pragma unroll
            for (int nt = 0; nt < 4; nt++) {
                const int nn = warp_n*32 + nt*8 + 2*(lane & 3);
                float vx = half ? acc[mt][nt][2] : acc[mt][nt][0];
                float vy = half ? acc[mt][nt][3] : acc[mt][nt][1];
                *(float2*)(C + (size_t)m*DM + n0 + nn) = make_float2(vx, vy);
            }
        }
    }
}

// ---------------------------------------------------------------------------
// RMS norm + RoPE; emits bf16 hi/lo pairs for the mma flash kernel.
// ---------------------------------------------------------------------------
__global__ void rms_rope_kernel(const float* __restrict__ cq, const float* __restrict__ sq,
                                const float* __restrict__ ck, const float* __restrict__ sk,
                                const float* __restrict__ qw, const float* __restrict__ kw)
{
    const int row = blockIdx.x;
    const int isk = blockIdx.y;
    const float* data = isk ? g_k : g_q;
    const float* cp = isk ? ck : cq;
    const float* sp = isk ? sk : sq;
    const float* w  = isk ? kw : qw;
    __nv_bfloat16* oh = isk ? g_khi : g_qhi;
    __nv_bfloat16* ol = isk ? g_klo : g_qlo;
    const int tid = threadIdx.x;
    const int s = row % SS;
    const int b = row / (HH*SS);

    __shared__ float smv[HD];
    __shared__ float red[4];
    float v = data[(size_t)row*HD + tid];
    float s2 = v*v;
    #pragma unroll
    for (int o = 16; o; o >>= 1) s2 += __shfl_xor_sync(0xffffffffu, s2, o);
    if ((tid & 31) == 0) red[tid >> 5] = s2;
    __syncthreads();
    const float var = (red[0]+red[1]+red[2]+red[3]) * (1.0f/HD);
    const float qn = v * rsqrtf(var + 1e-6f) * w[tid];
    smv[tid] = qn;
    __syncthreads();
    const float rot = (tid < 64) ? -smv[tid+64] : smv[tid-64];
    const size_t ci = ((size_t)b*SS + s)*HD + tid;
    const float val = qn * cp[ci] + rot * sp[ci];
    const uint32_t bits = __float_as_uint(val);
    const float hi = __uint_as_float(bits & 0xffff0000u);
    oh[(size_t)row*HD + tid] = __ushort_as_bfloat16((unsigned short)(bits >> 16));
    ol[(size_t)row*HD + tid] = __float2bfloat16_rn(val - hi);
}

// ---------------------------------------------------------------------------
// Flash attention on mma.sync. CTA = 128 queries, 8 warps x 16 rows.
// ---------------------------------------------------------------------------
#define FB_QH 0
#define FB_QL 32768
#define FB_ST 65536
#define ST_SZ 65536
#define T_KH 0
#define T_KL 16384
#define T_VH 32768
#define T_VL 49152
#define NKB (SS/64)
#define FLASH_DSMEM (FB_ST + 2*ST_SZ + 1024)

__global__ __launch_bounds__(256, 1)
void flash_mma()
{
    extern __shared__ char fsm_raw[];
    const uint32_t raw_u = smem_to_u32(fsm_raw);
    const uint32_t sb0 = (raw_u + 1023u) & ~1023u;
    char* bp = fsm_raw + (sb0 - raw_u);

    const int tid = threadIdx.x;
    const int wid = tid >> 5;
    const int lane = tid & 31;
    const int qb = blockIdx.x;
    const int bh = blockIdx.y;

    const size_t base = (size_t)bh * SS * HD;
    const char* Qh = (const char*)(g_qhi + base + (size_t)qb * 128 * HD);
    const char* Ql = (const char*)(g_qlo + base + (size_t)qb * 128 * HD);
    const char* Kh = (const char*)(g_khi + base);
    const char* Kl = (const char*)(g_klo + base);
    const char* Vh = (const char*)(g_vhi + base);
    const char* Vl = (const char*)(g_vlo + base);

    #pragma unroll
    for (int i = 0; i < 8; i++) {
        const int idx = tid + i*256;
        const int row = idx >> 4, c = idx & 15;
        const uint32_t d = SWZ256((uint32_t)(row*256 + c*16));
        *(uint4*)(bp + FB_QH + d) = *(const uint4*)(Qh + (size_t)row*256 + c*16);
        *(uint4*)(bp + FB_QL + d) = *(const uint4*)(Ql + (size_t)row*256 + c*16);
    }

    {
        const uint32_t sb = sb0 + FB_ST;
        #pragma unroll
        for (int j = 0; j < 4; j++) {
            const int idx = tid + j*256;
            const int row = idx >> 4, c = idx & 15;
            const uint32_t d = SWZ256((uint32_t)(row*256 + c*16));
            const size_t go = (size_t)row*256 + c*16;
            cpa16(sb + T_KH + d, Kh + go);
            cpa16(sb + T_KL + d, Kl + go);
            cpa16(sb + T_VH + d, Vh + go);
            cpa16(sb + T_VL + d, Vl + go);
        }
        CP_COMMIT();
    }

    float sacc[8][4];
    float oacc[16][4];
    #pragma unroll
    for (int i = 0; i < 16; i++)
        #pragma unroll
        for (int r = 0; r < 4; r++) oacc[i][r] = 0.f;
    float m0 = -1e30f, m1 = -1e30f, l0 = 0.f, l1 = 0.f;

    const int w16 = wid * 16;
    const uint32_t qa_off = (uint32_t)((w16 + (lane & 15))*256 + (lane >> 4)*16);
    const uint32_t kb_row = (uint32_t)(((lane >> 4) << 3) + (lane & 7));
    const uint32_t kb_cs = (uint32_t)(((lane >> 3) & 1) * 16);
    const uint32_t vb_row = (uint32_t)((lane & 7) + (((lane >> 3) & 1) << 3));
    const uint32_t vb_cs = (uint32_t)((lane >> 4) * 16);
    const float sc = 0.08838834764831845f;

    for (int kb = 0; kb < NKB; kb++) {
        if (kb > 0) __syncthreads();
        if (kb + 1 < NKB) {
            const uint32_t sb = sb0 + FB_ST + ((kb+1) & 1) * ST_SZ;
            const size_t kbase = (size_t)(kb+1) * 64 * 256;
            #pragma unroll
            for (int j = 0; j < 4; j++) {
                const int idx = tid + j*256;
                const int row = idx >> 4, c = idx & 15;
                const uint32_t d = SWZ256((uint32_t)(row*256 + c*16));
                const size_t go = kbase + (size_t)row*256 + c*16;
                cpa16(sb + T_KH + d, Kh + go);
                cpa16(sb + T_KL + d, Kl + go);
                cpa16(sb + T_VH + d, Vh + go);
                cpa16(sb + T_VL + d, Vl + go);
            }
            CP_COMMIT();
            CP_WAIT1();
        } else {
            CP_WAIT0();
        }
        __syncthreads();

        const uint32_t sb = sb0 + FB_ST + (kb & 1) * ST_SZ;

        #pragma unroll
        for (int i = 0; i < 8; i++)
            #pragma unroll
            for (int r = 0; r < 4; r++) sacc[i][r] = 0.f;

        #pragma unroll
        for (int kk = 0; kk < 8; kk++) {
            uint32_t qh4[4], ql4[4];
            const uint32_t qa = sb0 + FB_QH + SWZ256(qa_off + (uint32_t)kk*32);
            ldmx4(qh4[0], qh4[1], qh4[2], qh4[3], qa);
            ldmx4(ql4[0], ql4[1], ql4[2], ql4[3], qa + (FB_QL - FB_QH));
            #pragma unroll
            for (int n16 = 0; n16 < 4; n16++) {
                uint32_t kh4[4], kl4[4];
                const uint32_t ka = sb + T_KH +
                    SWZ256((uint32_t)((n16*16 + kb_row)*256 + kk*32 + kb_cs));
                ldmx4(kh4[0], kh4[1], kh4[2], kh4[3], ka);
                ldmx4(kl4[0], kl4[1], kl4[2], kl4[3], ka + (T_KL - T_KH));
                mma16816(sacc[2*n16],   qh4, &kh4[0]);
                mma16816(sacc[2*n16],   qh4, &kl4[0]);
                mma16816(sacc[2*n16],   ql4, &kh4[0]);
                mma16816(sacc[2*n16+1], qh4, &kh4[2]);
                mma16816(sacc[2*n16+1], qh4, &kl4[2]);
                mma16816(sacc[2*n16+1], ql4, &kh4[2]);
            }
        }

        #pragma unroll
        for (int i = 0; i < 8; i++)
            #pragma unroll
            for (int r = 0; r < 4; r++) sacc[i][r] *= sc;

        float nm0 = -1e30f, nm1 = -1e30f;
        #pragma unroll
        for (int i = 0; i < 8; i++) {
            nm0 = fmaxf(nm0, fmaxf(sacc[i][0], sacc[i][1]));
            nm1 = fmaxf(nm1, fmaxf(sacc[i][2], sacc[i][3]));
        }
        nm0 = fmaxf(nm0, __shfl_xor_sync(0xffffffffu, nm0, 1));
        nm0 = fmaxf(nm0, __shfl_xor_sync(0xffffffffu, nm0, 2));
        nm1 = fmaxf(nm1, __shfl_xor_sync(0xffffffffu, nm1, 1));
        nm1 = fmaxf(nm1, __shfl_xor_sync(0xffffffffu, nm1, 2));
        const float mn0 = fmaxf(m0, nm0), mn1 = fmaxf(m1, nm1);
        const float a0 = __expf(m0 - mn0), a1 = __expf(m1 - mn1);
        m0 = mn0; m1 = mn1;
        float ls0 = 0.f, ls1 = 0.f;
        #pragma unroll
        for (int i = 0; i < 8; i++) {
            float p0 = __expf(sacc[i][0] - m0); sacc[i][0] = p0; ls0 += p0;
            float p1 = __expf(sacc[i][1] - m0); sacc[i][1] = p1; ls0 += p1;
            float p2 = __expf(sacc[i][2] - m1); sacc[i][2] = p2; ls1 += p2;
            float p3 = __expf(sacc[i][3] - m1); sacc[i][3] = p3; ls1 += p3;
        }
        ls0 += __shfl_xor_sync(0xffffffffu, ls0, 1);
        ls0 += __shfl_xor_sync(0xffffffffu, ls0, 2);
        ls1 += __shfl_xor_sync(0xffffffffu, ls1, 1);
        ls1 += __shfl_xor_sync(0xffffffffu, ls1, 2);
        l0 = l0*a0 + ls0;
        l1 = l1*a1 + ls1;
        #pragma unroll
        for (int i = 0; i < 16; i++) {
            oacc[i][0] *= a0; oacc[i][1] *= a0;
            oacc[i][2] *= a1; oacc[i][3] *= a1;
        }

        #pragma unroll
        for (int kk = 0; kk < 4; kk++) {
            uint32_t ph[4], pl[4];
            ph[0] = pack_hi(sacc[2*kk][0],   sacc[2*kk][1]);
            pl[0] = pack_lo(sacc[2*kk][0],   sacc[2*kk][1]);
            ph[1] = pack_hi(sacc[2*kk][2],   sacc[2*kk][3]);
            pl[1] = pack_lo(sacc[2*kk][2],   sacc[2*kk][3]);
            ph[2] = pack_hi(sacc[2*kk+1][0], sacc[2*kk+1][1]);
            pl[2] = pack_lo(sacc[2*kk+1][0], sacc[2*kk+1][1]);
            ph[3] = pack_hi(sacc[2*kk+1][2], sacc[2*kk+1][3]);
            pl[3] = pack_lo(sacc[2*kk+1][2], sacc[2*kk+1][3]);
            #pragma unroll
            for (int n16 = 0; n16 < 8; n16++) {
                uint32_t vh4[4], vl4[4];
                const uint32_t va = sb + T_VH +
                    SWZ256((uint32_t)((kk*16 + vb_row)*256 + n16*32 + vb_cs));
                ldmx4t(vh4[0], vh4[1], vh4[2], vh4[3], va);
                ldmx4t(vl4[0], vl4[1], vl4[2], vl4[3], va + (T_VL - T_VH));
                mma16816(oacc[2*n16],   ph, &vh4[0]);
                mma16816(oacc[2*n16],   pl, &vh4[0]);
                mma16816(oacc[2*n16],   ph, &vl4[0]);
                mma16816(oacc[2*n16+1], ph, &vh4[2]);
                mma16816(oacc[2*n16+1], pl, &vh4[2]);
                mma16816(oacc[2*n16+1], ph, &vl4[2]);
            }
        }
    }

    const int b = bh / HH, h = bh % HH;
    const int g = lane >> 2;
    const int col0 = (lane & 3) * 2;
    const float li0 = 1.0f / l0, li1 = 1.0f / l1;
    const int s0 = qb*128 + w16 + g;
    const size_t yb0 = ((size_t)(b*SS + s0)*HH + h)*HD;
    const size_t yb1 = ((size_t)(b*SS + s0 + 8)*HH + h)*HD;
    #pragma unroll
    for (int nt = 0; nt < 16; nt++) {
        const int c = nt*8 + col0;
        const float x0 = oacc[nt][0]*li0, y0 = oacc[nt][1]*li0;
        const float x1 = oacc[nt][2]*li1, y1 = oacc[nt][3]*li1;
        *(uint32_t*)(g_yhi + yb0 + c) = pack_hi(x0, y0);
        *(uint32_t*)(g_ylo + yb0 + c) = pack_lo(x0, y0);
        *(uint32_t*)(g_yhi + yb1 + c) = pack_hi(x1, y1);
        *(uint32_t*)(g_ylo + yb1 + c) = pack_lo(x1, y1);
    }
}

// ---------------------------------------------------------------------------
extern "C" void kernel_launch(void* const* d_in, const int* in_sizes, int n_in,
                              void* d_out, int out_size)
{
    const float* x   = (const float*)d_in[0];
    const float* ctx = (const float*)d_in[1];
    const float* cq  = (const float*)d_in[2];
    const float* sq  = (const float*)d_in[3];
    const float* ck  = (const float*)d_in[4];
    const float* sk  = (const float*)d_in[5];
    const float* Wq  = (const float*)d_in[6];
    const float* Wk  = (const float*)d_in[7];
    const float* Wv  = (const float*)d_in[8];
    const float* Wo  = (const float*)d_in[9];
    const float* qw  = (const float*)d_in[10];
    const float* kw  = (const float*)d_in[11];
    float* out = (float*)d_out;

    cudaFuncSetAttribute(qkv_kernel, cudaFuncAttributeMaxDynamicSharedMemorySize, GEMM_DSMEM);
    cudaFuncSetAttribute(wo_kernel,  cudaFuncAttributeMaxDynamicSharedMemorySize, GEMM_DSMEM);
    cudaFuncSetAttribute(flash_mma,  cudaFuncAttributeMaxDynamicSharedMemorySize, FLASH_DSMEM);

    cvt6_kernel<<<32768, 256>>>(x, ctx, Wq, Wk, Wv, Wo);

    dim3 gq3(DM/128, NROWS/128, 3);     // (16, 32, 3)
    qkv_kernel<<<gq3, 256, GEMM_DSMEM>>>();
    rms_rope_kernel<<<dim3(BB*HH*SS, 2), HD>>>(cq, sq, ck, sk, qw, kw);
    flash_mma<<<dim3(SS/128, BB*HH), 256, FLASH_DSMEM>>>();
    dim3 gg(DM/128, NROWS/128);         // (16, 32)
    wo_kernel<<<gg, 256, GEMM_DSMEM>>>(out);
}

// round 7
// speedup vs baseline: 3.3104x; 1.0946x over previous
#include <cuda_runtime.h>
#include <cuda_bf16.h>
#include <cstdint>

#define BB 2
#define SS 2048
#define DM 2048
#define HH 16
#define HD 128
#define NROWS (BB*SS)

// ---------------------------------------------------------------------------
// Helpers (plain sm_80-era PTX only: ldmatrix / mma.sync / cp.async)
// ---------------------------------------------------------------------------
__device__ __forceinline__ uint32_t smem_to_u32(const void* p) {
    uint32_t a;
    asm("{ .reg .u64 t; cvta.to.shared.u64 t, %1; cvt.u32.u64 %0, t; }" : "=r"(a) : "l"(p));
    return a;
}
#define SWZ128(off) ((off) ^ (((off) >> 3) & 0x70))
#define SWZ256(off) ((off) ^ ((((off) >> 8) & 7) << 4))

__device__ __forceinline__ void cpa16(uint32_t s, const void* g) {
    asm volatile("cp.async.cg.shared.global [%0], [%1], 16;" :: "r"(s), "l"(g));
}
#define CP_COMMIT() asm volatile("cp.async.commit_group;" ::: "memory")
#define CP_WAIT1()  asm volatile("cp.async.wait_group 1;" ::: "memory")
#define CP_WAIT0()  asm volatile("cp.async.wait_group 0;" ::: "memory")

__device__ __forceinline__ void ldmx4(uint32_t& r0, uint32_t& r1, uint32_t& r2, uint32_t& r3,
                                      uint32_t addr) {
    asm volatile("ldmatrix.sync.aligned.m8n8.x4.shared.b16 {%0,%1,%2,%3}, [%4];"
                 : "=r"(r0), "=r"(r1), "=r"(r2), "=r"(r3) : "r"(addr));
}
__device__ __forceinline__ void ldmx4t(uint32_t& r0, uint32_t& r1, uint32_t& r2, uint32_t& r3,
                                       uint32_t addr) {
    asm volatile("ldmatrix.sync.aligned.m8n8.x4.trans.shared.b16 {%0,%1,%2,%3}, [%4];"
                 : "=r"(r0), "=r"(r1), "=r"(r2), "=r"(r3) : "r"(addr));
}
__device__ __forceinline__ void mma16816(float* c, const uint32_t* a, const uint32_t* b) {
    asm volatile("mma.sync.aligned.m16n8k16.row.col.f32.bf16.bf16.f32 "
                 "{%0,%1,%2,%3}, {%4,%5,%6,%7}, {%8,%9}, {%0,%1,%2,%3};"
                 : "+f"(c[0]), "+f"(c[1]), "+f"(c[2]), "+f"(c[3])
                 : "r"(a[0]), "r"(a[1]), "r"(a[2]), "r"(a[3]), "r"(b[0]), "r"(b[1]));
}

__device__ __forceinline__ uint32_t pack_rn(float a, float b) {
    __nv_bfloat162 t = __float22bfloat162_rn(make_float2(a, b));
    return *(uint32_t*)&t;
}
__device__ __forceinline__ uint32_t pack_hi(float a, float b) {
    return __byte_perm(__float_as_uint(a), __float_as_uint(b), 0x7632);
}
__device__ __forceinline__ uint32_t pack_lo(float a, float b) {
    float ra = a - __uint_as_float(__float_as_uint(a) & 0xffff0000u);
    float rb = b - __uint_as_float(__float_as_uint(b) & 0xffff0000u);
    return pack_rn(ra, rb);
}

// ---------------------------------------------------------------------------
// Device scratch
// ---------------------------------------------------------------------------
__device__ __align__(256) float g_q[(size_t)BB*HH*SS*HD];
__device__ __align__(256) float g_k[(size_t)BB*HH*SS*HD];
__device__ __align__(256) __nv_bfloat16 g_xhi[(size_t)NROWS*DM];
__device__ __align__(256) __nv_bfloat16 g_xlo[(size_t)NROWS*DM];
__device__ __align__(256) __nv_bfloat16 g_chi[(size_t)NROWS*DM];
__device__ __align__(256) __nv_bfloat16 g_clo[(size_t)NROWS*DM];
__device__ __align__(256) __nv_bfloat16 g_wqh[DM*DM], g_wql[DM*DM];
__device__ __align__(256) __nv_bfloat16 g_wkh[DM*DM], g_wkl[DM*DM];
__device__ __align__(256) __nv_bfloat16 g_wvh[DM*DM], g_wvl[DM*DM];
__device__ __align__(256) __nv_bfloat16 g_woh[DM*DM], g_wol[DM*DM];
__device__ __align__(256) __nv_bfloat16 g_qhi[(size_t)BB*HH*SS*HD], g_qlo[(size_t)BB*HH*SS*HD];
__device__ __align__(256) __nv_bfloat16 g_khi[(size_t)BB*HH*SS*HD], g_klo[(size_t)BB*HH*SS*HD];
__device__ __align__(256) __nv_bfloat16 g_vhi[(size_t)BB*HH*SS*HD], g_vlo[(size_t)BB*HH*SS*HD];
__device__ __align__(256) __nv_bfloat16 g_yhi[(size_t)NROWS*DM];
__device__ __align__(256) __nv_bfloat16 g_ylo[(size_t)NROWS*DM];

// ---------------------------------------------------------------------------
// Fused fp32 -> bf16 hi/lo conversion for all 6 tensors (segmented grid).
// ---------------------------------------------------------------------------
__global__ void cvt6_kernel(const float* __restrict__ x, const float* __restrict__ ctx,
                            const float* __restrict__ Wq, const float* __restrict__ Wk,
                            const float* __restrict__ Wv, const float* __restrict__ Wo)
{
    int bid = blockIdx.x;
    const float* src;
    __nv_bfloat16 *hi, *lo;
    int lb;
    if (bid < 8192)       { src = x;   hi = g_xhi; lo = g_xlo; lb = bid; }
    else if (bid < 16384) { src = ctx; hi = g_chi; lo = g_clo; lb = bid - 8192; }
    else if (bid < 20480) { src = Wq;  hi = g_wqh; lo = g_wql; lb = bid - 16384; }
    else if (bid < 24576) { src = Wk;  hi = g_wkh; lo = g_wkl; lb = bid - 20480; }
    else if (bid < 28672) { src = Wv;  hi = g_wvh; lo = g_wvl; lb = bid - 24576; }
    else                  { src = Wo;  hi = g_woh; lo = g_wol; lb = bid - 28672; }
    const int i = lb*256 + threadIdx.x;
    float4 v = ((const float4*)src)[i];
    ((uint2*)hi)[i] = make_uint2(pack_hi(v.x, v.y), pack_hi(v.z, v.w));
    ((uint2*)lo)[i] = make_uint2(pack_lo(v.x, v.y), pack_lo(v.z, v.w));
}

// ---------------------------------------------------------------------------
// 3-stage bf16-pair GEMM mainloop, 16 warps (512 thr), warp tile 32x32.
// CTA 128x128, KC=64, 3 HMMA products per tile.
// ---------------------------------------------------------------------------
#define KC 64
#define NSTG (DM/KC)
#define AH_OFF 0
#define AL_OFF 16384
#define BH_OFF 32768
#define BL_OFF 49152
#define STG_BYTES 65536
#define GEMM_DSMEM (3*STG_BYTES + 1024)

__device__ __forceinline__ void gemm_body(
    const __nv_bfloat16* __restrict__ Ah, const __nv_bfloat16* __restrict__ Al,
    const __nv_bfloat16* __restrict__ Bh, const __nv_bfloat16* __restrict__ Bl,
    uint32_t sbase, int m0, int n0, float acc[2][4][4])
{
    const int tid = threadIdx.x;
    const int wid = tid >> 5;            // 0..15
    const int lane = tid & 31;
    const int warp_m = wid >> 2;         // 0..3 (32 rows)
    const int warp_n = wid & 3;          // 0..3 (32 cols)

    // prefetch assignment: 512 threads; row = tid>>2 (0..127), quarter = tid&3
    const int prow = tid >> 2;
    const int pq = tid & 3;              // 2 chunks of 16B each
    const size_t gA = (size_t)(m0 + prow) * DM + pq * 16;
    const size_t gB = (size_t)(n0 + prow) * DM + pq * 16;
    const uint32_t swp[2] = {
        SWZ128((uint32_t)(prow*128 + (pq*2 + 0)*16)),
        SWZ128((uint32_t)(prow*128 + (pq*2 + 1)*16)) };

    // prologue: prefetch stages 0, 1
    #pragma unroll
    for (int s = 0; s < 2; s++) {
        const uint32_t buf = sbase + s * STG_BYTES;
        const size_t ko = (size_t)s * KC;
        #pragma unroll
        for (int c = 0; c < 2; c++) {
            const size_t go = ko + (size_t)c * 8;
            cpa16(buf + AH_OFF + swp[c], Ah + gA + go);
            cpa16(buf + AL_OFF + swp[c], Al + gA + go);
            cpa16(buf + BH_OFF + swp[c], Bh + gB + go);
            cpa16(buf + BL_OFF + swp[c], Bl + gB + go);
        }
        CP_COMMIT();
    }

    const int a_r = warp_m*32 + (lane & 15);
    const int a_cs = lane >> 4;
    const int b_r = warp_n*32 + ((lane >> 4) << 3) + (lane & 7);
    const int b_cs = (lane >> 3) & 1;

    int sbuf = 0;
    for (int s = 0; s < NSTG; s++) {
        CP_WAIT1();
        __syncthreads();
        if (s + 2 < NSTG) {
            const int wbuf = (sbuf + 2 >= 3) ? (sbuf - 1) : (sbuf + 2);
            const uint32_t buf = sbase + wbuf * STG_BYTES;
            const size_t ko = (size_t)(s+2) * KC;
            #pragma unroll
            for (int c = 0; c < 2; c++) {
                const size_t go = ko + (size_t)c * 8;
                cpa16(buf + AH_OFF + swp[c], Ah + gA + go);
                cpa16(buf + AL_OFF + swp[c], Al + gA + go);
                cpa16(buf + BH_OFF + swp[c], Bh + gB + go);
                cpa16(buf + BL_OFF + swp[c], Bl + gB + go);
            }
            CP_COMMIT();
        }

        const uint32_t buf = sbase + sbuf * STG_BYTES;
        #pragma unroll
        for (int ks = 0; ks < 4; ks++) {
            const int kc = ks * 2;
            uint32_t ah[2][4], al_[2][4], bh[4][2], bl[4][2];
            #pragma unroll
            for (int mt = 0; mt < 2; mt++) {
                const uint32_t off = (uint32_t)((a_r + mt*16)*128 + (kc + a_cs)*16);
                ldmx4(ah[mt][0], ah[mt][1], ah[mt][2], ah[mt][3], buf + AH_OFF + SWZ128(off));
                ldmx4(al_[mt][0], al_[mt][1], al_[mt][2], al_[mt][3], buf + AL_OFF + SWZ128(off));
            }
            #pragma unroll
            for (int np = 0; np < 2; np++) {
                const uint32_t off = (uint32_t)((b_r + np*16)*128 + (kc + b_cs)*16);
                ldmx4(bh[np*2][0], bh[np*2][1], bh[np*2+1][0], bh[np*2+1][1],
                      buf + BH_OFF + SWZ128(off));
                ldmx4(bl[np*2][0], bl[np*2][1], bl[np*2+1][0], bl[np*2+1][1],
                      buf + BL_OFF + SWZ128(off));
            }
            #pragma unroll
            for (int mt = 0; mt < 2; mt++)
                #pragma unroll
                for (int nt = 0; nt < 4; nt++) {
                    mma16816(acc[mt][nt], ah[mt], bh[nt]);
                    mma16816(acc[mt][nt], ah[mt], bl[nt]);
                    mma16816(acc[mt][nt], al_[mt], bh[nt]);
                }
        }
        sbuf = (sbuf + 1 >= 3) ? 0 : (sbuf + 1);
    }
}

// ---------------------------------------------------------------------------
// Fused Q/K/V projection: blockIdx.z selects operand set + epilogue.
// ---------------------------------------------------------------------------
__global__ __launch_bounds__(512, 1)
void qkv_kernel()
{
    extern __shared__ char dsm_raw[];
    const uint32_t raw_u = smem_to_u32(dsm_raw);
    const uint32_t sbase = (raw_u + 1023u) & ~1023u;

    const int z = blockIdx.z;
    const __nv_bfloat16 *Ah, *Al, *Bh, *Bl;
    if (z == 0)      { Ah = g_xhi; Al = g_xlo; Bh = g_wqh; Bl = g_wql; }
    else if (z == 1) { Ah = g_chi; Al = g_clo; Bh = g_wkh; Bl = g_wkl; }
    else             { Ah = g_chi; Al = g_clo; Bh = g_wvh; Bl = g_wvl; }

    const int m0 = blockIdx.y * 128;
    const int n0 = blockIdx.x * 128;

    float acc[2][4][4];
    #pragma unroll
    for (int i = 0; i < 2; i++)
        #pragma unroll
        for (int j = 0; j < 4; j++)
            #pragma unroll
            for (int r = 0; r < 4; r++) acc[i][j][r] = 0.f;

    gemm_body(Ah, Al, Bh, Bl, sbase, m0, n0, acc);

    const int tid = threadIdx.x;
    const int wid = tid >> 5;
    const int lane = tid & 31;
    const int warp_m = wid >> 2;
    const int warp_n = wid & 3;

    #pragma unroll
    for (int mt = 0; mt < 2; mt++) {
        const int mrow = m0 + warp_m*32 + mt*16 + (lane >> 2);
        #pragma unroll
        for (int half = 0; half < 2; half++) {
            const int m = mrow + half*8;
            const int b = m >> 11, sidx = m & (SS - 1);
            const size_t rb = ((size_t)((b*HH + blockIdx.x)*SS + sidx))*HD;
            #pragma unroll
            for (int nt = 0; nt < 4; nt++) {
                const int nn = warp_n*32 + nt*8 + 2*(lane & 3);
                float vx = half ? acc[mt][nt][2] : acc[mt][nt][0];
                float vy = half ? acc[mt][nt][3] : acc[mt][nt][1];
                if (z == 0) {
                    *(float2*)(g_q + rb + nn) = make_float2(vx, vy);
                } else if (z == 1) {
                    *(float2*)(g_k + rb + nn) = make_float2(vx, vy);
                } else {
                    *(uint32_t*)(g_vhi + rb + nn) = pack_hi(vx, vy);
                    *(uint32_t*)(g_vlo + rb + nn) = pack_lo(vx, vy);
                }
            }
        }
    }
}

// ---------------------------------------------------------------------------
// Output projection: out = y @ Wo^T, fp32 result.
// ---------------------------------------------------------------------------
__global__ __launch_bounds__(512, 1)
void wo_kernel(float* __restrict__ C)
{
    extern __shared__ char dsm_raw[];
    const uint32_t raw_u = smem_to_u32(dsm_raw);
    const uint32_t sbase = (raw_u + 1023u) & ~1023u;

    const int m0 = blockIdx.y * 128;
    const int n0 = blockIdx.x * 128;

    float acc[2][4][4];
    #pragma unroll
    for (int i = 0; i < 2; i++)
        #pragma unroll
        for (int j = 0; j < 4; j++)
            #pragma unroll
            for (int r = 0; r < 4; r++) acc[i][j][r] = 0.f;

    gemm_body(g_yhi, g_ylo, g_woh, g_wol, sbase, m0, n0, acc);

    const int tid = threadIdx.x;
    const int wid = tid >> 5;
    const int lane = tid & 31;
    const int warp_m = wid >> 2;
    const int warp_n = wid & 3;

    #pragma unroll
    for (int mt = 0; mt < 2; mt++) {
        const int mrow = m0 + warp_m*32 + mt*16 + (lane >> 2);
        #pragma unroll
        for (int half = 0; half < 2; half++) {
            const int m = mrow + half*8;
            #pragma unroll
            for (int nt = 0; nt < 4; nt++) {
                const int nn = warp_n*32 + nt*8 + 2*(lane & 3);
                float vx = half ? acc[mt][nt][2] : acc[mt][nt][0];
                float vy = half ? acc[mt][nt][3] : acc[mt][nt][1];
                *(float2*)(C + (size_t)m*DM + n0 + nn) = make_float2(vx, vy);
            }
        }
    }
}

// ---------------------------------------------------------------------------
// RMS norm + RoPE; emits bf16 hi/lo pairs for the mma flash kernel.
// ---------------------------------------------------------------------------
__global__ void rms_rope_kernel(const float* __restrict__ cq, const float* __restrict__ sq,
                                const float* __restrict__ ck, const float* __restrict__ sk,
                                const float* __restrict__ qw, const float* __restrict__ kw)
{
    const int row = blockIdx.x;
    const int isk = blockIdx.y;
    const float* data = isk ? g_k : g_q;
    const float* cp = isk ? ck : cq;
    const float* sp = isk ? sk : sq;
    const float* w  = isk ? kw : qw;
    __nv_bfloat16* oh = isk ? g_khi : g_qhi;
    __nv_bfloat16* ol = isk ? g_klo : g_qlo;
    const int tid = threadIdx.x;
    const int s = row % SS;
    const int b = row / (HH*SS);

    __shared__ float smv[HD];
    __shared__ float red[4];
    float v = data[(size_t)row*HD + tid];
    float s2 = v*v;
    #pragma unroll
    for (int o = 16; o; o >>= 1) s2 += __shfl_xor_sync(0xffffffffu, s2, o);
    if ((tid & 31) == 0) red[tid >> 5] = s2;
    __syncthreads();
    const float var = (red[0]+red[1]+red[2]+red[3]) * (1.0f/HD);
    const float qn = v * rsqrtf(var + 1e-6f) * w[tid];
    smv[tid] = qn;
    __syncthreads();
    const float rot = (tid < 64) ? -smv[tid+64] : smv[tid-64];
    const size_t ci = ((size_t)b*SS + s)*HD + tid;
    const float val = qn * cp[ci] + rot * sp[ci];
    const uint32_t bits = __float_as_uint(val);
    const float hi = __uint_as_float(bits & 0xffff0000u);
    oh[(size_t)row*HD + tid] = __ushort_as_bfloat16((unsigned short)(bits >> 16));
    ol[(size_t)row*HD + tid] = __float2bfloat16_rn(val - hi);
}

// ---------------------------------------------------------------------------
// Flash attention on mma.sync. CTA = 128 queries, 8 warps x 16 rows.
// (unchanged from R6)
// ---------------------------------------------------------------------------
#define FB_QH 0
#define FB_QL 32768
#define FB_ST 65536
#define ST_SZ 65536
#define T_KH 0
#define T_KL 16384
#define T_VH 32768
#define T_VL 49152
#define NKB (SS/64)
#define FLASH_DSMEM (FB_ST + 2*ST_SZ + 1024)

__global__ __launch_bounds__(256, 1)
void flash_mma()
{
    extern __shared__ char fsm_raw[];
    const uint32_t raw_u = smem_to_u32(fsm_raw);
    const uint32_t sb0 = (raw_u + 1023u) & ~1023u;
    char* bp = fsm_raw + (sb0 - raw_u);

    const int tid = threadIdx.x;
    const int wid = tid >> 5;
    const int lane = tid & 31;
    const int qb = blockIdx.x;
    const int bh = blockIdx.y;

    const size_t base = (size_t)bh * SS * HD;
    const char* Qh = (const char*)(g_qhi + base + (size_t)qb * 128 * HD);
    const char* Ql = (const char*)(g_qlo + base + (size_t)qb * 128 * HD);
    const char* Kh = (const char*)(g_khi + base);
    const char* Kl = (const char*)(g_klo + base);
    const char* Vh = (const char*)(g_vhi + base);
    const char* Vl = (const char*)(g_vlo + base);

    #pragma unroll
    for (int i = 0; i < 8; i++) {
        const int idx = tid + i*256;
        const int row = idx >> 4, c = idx & 15;
        const uint32_t d = SWZ256((uint32_t)(row*256 + c*16));
        *(uint4*)(bp + FB_QH + d) = *(const uint4*)(Qh + (size_t)row*256 + c*16);
        *(uint4*)(bp + FB_QL + d) = *(const uint4*)(Ql + (size_t)row*256 + c*16);
    }

    {
        const uint32_t sb = sb0 + FB_ST;
        #pragma unroll
        for (int j = 0; j < 4; j++) {
            const int idx = tid + j*256;
            const int row = idx >> 4, c = idx & 15;
            const uint32_t d = SWZ256((uint32_t)(row*256 + c*16));
            const size_t go = (size_t)row*256 + c*16;
            cpa16(sb + T_KH + d, Kh + go);
            cpa16(sb + T_KL + d, Kl + go);
            cpa16(sb + T_VH + d, Vh + go);
            cpa16(sb + T_VL + d, Vl + go);
        }
        CP_COMMIT();
    }

    float sacc[8][4];
    float oacc[16][4];
    #pragma unroll
    for (int i = 0; i < 16; i++)
        #pragma unroll
        for (int r = 0; r < 4; r++) oacc[i][r] = 0.f;
    float m0 = -1e30f, m1 = -1e30f, l0 = 0.f, l1 = 0.f;

    const int w16 = wid * 16;
    const uint32_t qa_off = (uint32_t)((w16 + (lane & 15))*256 + (lane >> 4)*16);
    const uint32_t kb_row = (uint32_t)(((lane >> 4) << 3) + (lane & 7));
    const uint32_t kb_cs = (uint32_t)(((lane >> 3) & 1) * 16);
    const uint32_t vb_row = (uint32_t)((lane & 7) + (((lane >> 3) & 1) << 3));
    const uint32_t vb_cs = (uint32_t)((lane >> 4) * 16);
    const float sc = 0.08838834764831845f;

    for (int kb = 0; kb < NKB; kb++) {
        if (kb > 0) __syncthreads();
        if (kb + 1 < NKB) {
            const uint32_t sb = sb0 + FB_ST + ((kb+1) & 1) * ST_SZ;
            const size_t kbase = (size_t)(kb+1) * 64 * 256;
            #pragma unroll
            for (int j = 0; j < 4; j++) {
                const int idx = tid + j*256;
                const int row = idx >> 4, c = idx & 15;
                const uint32_t d = SWZ256((uint32_t)(row*256 + c*16));
                const size_t go = kbase + (size_t)row*256 + c*16;
                cpa16(sb + T_KH + d, Kh + go);
                cpa16(sb + T_KL + d, Kl + go);
                cpa16(sb + T_VH + d, Vh + go);
                cpa16(sb + T_VL + d, Vl + go);
            }
            CP_COMMIT();
            CP_WAIT1();
        } else {
            CP_WAIT0();
        }
        __syncthreads();

        const uint32_t sb = sb0 + FB_ST + (kb & 1) * ST_SZ;

        #pragma unroll
        for (int i = 0; i < 8; i++)
            #pragma unroll
            for (int r = 0; r < 4; r++) sacc[i][r] = 0.f;

        #pragma unroll
        for (int kk = 0; kk < 8; kk++) {
            uint32_t qh4[4], ql4[4];
            const uint32_t qa = sb0 + FB_QH + SWZ256(qa_off + (uint32_t)kk*32);
            ldmx4(qh4[0], qh4[1], qh4[2], qh4[3], qa);
            ldmx4(ql4[0], ql4[1], ql4[2], ql4[3], qa + (FB_QL - FB_QH));
            #pragma unroll
            for (int n16 = 0; n16 < 4; n16++) {
                uint32_t kh4[4], kl4[4];
                const uint32_t ka = sb + T_KH +
                    SWZ256((uint32_t)((n16*16 + kb_row)*256 + kk*32 + kb_cs));
                ldmx4(kh4[0], kh4[1], kh4[2], kh4[3], ka);
                ldmx4(kl4[0], kl4[1], kl4[2], kl4[3], ka + (T_KL - T_KH));
                mma16816(sacc[2*n16],   qh4, &kh4[0]);
                mma16816(sacc[2*n16],   qh4, &kl4[0]);
                mma16816(sacc[2*n16],   ql4, &kh4[0]);
                mma16816(sacc[2*n16+1], qh4, &kh4[2]);
                mma16816(sacc[2*n16+1], qh4, &kl4[2]);
                mma16816(sacc[2*n16+1], ql4, &kh4[2]);
            }
        }

        #pragma unroll
        for (int i = 0; i < 8; i++)
            #pragma unroll
            for (int r = 0; r < 4; r++) sacc[i][r] *= sc;

        float nm0 = -1e30f, nm1 = -1e30f;
        #pragma unroll
        for (int i = 0; i < 8; i++) {
            nm0 = fmaxf(nm0, fmaxf(sacc[i][0], sacc[i][1]));
            nm1 = fmaxf(nm1, fmaxf(sacc[i][2], sacc[i][3]));
        }
        nm0 = fmaxf(nm0, __shfl_xor_sync(0xffffffffu, nm0, 1));
        nm0 = fmaxf(nm0, __shfl_xor_sync(0xffffffffu, nm0, 2));
        nm1 = fmaxf(nm1, __shfl_xor_sync(0xffffffffu, nm1, 1));
        nm1 = fmaxf(nm1, __shfl_xor_sync(0xffffffffu, nm1, 2));
        const float mn0 = fmaxf(m0, nm0), mn1 = fmaxf(m1, nm1);
        const float a0 = __expf(m0 - mn0), a1 = __expf(m1 - mn1);
        m0 = mn0; m1 = mn1;
        float ls0 = 0.f, ls1 = 0.f;
        #pragma unroll
        for (int i = 0; i < 8; i++) {
            float p0 = __expf(sacc[i][0] - m0); sacc[i][0] = p0; ls0 += p0;
            float p1 = __expf(sacc[i][1] - m0); sacc[i][1] = p1; ls0 += p1;
            float p2 = __expf(sacc[i][2] - m1); sacc[i][2] = p2; ls1 += p2;
            float p3 = __expf(sacc[i][3] - m1); sacc[i][3] = p3; ls1 += p3;
        }
        ls0 += __shfl_xor_sync(0xffffffffu, ls0, 1);
        ls0 += __shfl_xor_sync(0xffffffffu, ls0, 2);
        ls1 += __shfl_xor_sync(0xffffffffu, ls1, 1);
        ls1 += __shfl_xor_sync(0xffffffffu, ls1, 2);
        l0 = l0*a0 + ls0;
        l1 = l1*a1 + ls1;
        #pragma unroll
        for (int i = 0; i < 16; i++) {
            oacc[i][0] *= a0; oacc[i][1] *= a0;
            oacc[i][2] *= a1; oacc[i][3] *= a1;
        }

        #pragma unroll
        for (int kk = 0; kk < 4; kk++) {
            uint32_t ph[4], pl[4];
            ph[0] = pack_hi(sacc[2*kk][0],   sacc[2*kk][1]);
            pl[0] = pack_lo(sacc[2*kk][0],   sacc[2*kk][1]);
            ph[1] = pack_hi(sacc[2*kk][2],   sacc[2*kk][3]);
            pl[1] = pack_lo(sacc[2*kk][2],   sacc[2*kk][3]);
            ph[2] = pack_hi(sacc[2*kk+1][0], sacc[2*kk+1][1]);
            pl[2] = pack_lo(sacc[2*kk+1][0], sacc[2*kk+1][1]);
            ph[3] = pack_hi(sacc[2*kk+1][2], sacc[2*kk+1][3]);
            pl[3] = pack_lo(sacc[2*kk+1][2], sacc[2*kk+1][3]);
            #pragma unroll
            for (int n16 = 0; n16 < 8; n16++) {
                uint32_t vh4[4], vl4[4];
                const uint32_t va = sb + T_VH +
                    SWZ256((uint32_t)((kk*16 + vb_row)*256 + n16*32 + vb_cs));
                ldmx4t(vh4[0], vh4[1], vh4[2], vh4[3], va);
                ldmx4t(vl4[0], vl4[1], vl4[2], vl4[3], va + (T_VL - T_VH));
                mma16816(oacc[2*n16],   ph, &vh4[0]);
                mma16816(oacc[2*n16],   pl, &vh4[0]);
                mma16816(oacc[2*n16],   ph, &vl4[0]);
                mma16816(oacc[2*n16+1], ph, &vh4[2]);
                mma16816(oacc[2*n16+1], pl, &vh4[2]);
                mma16816(oacc[2*n16+1], ph, &vl4[2]);
            }
        }
    }

    const int b = bh / HH, h = bh % HH;
    const int g = lane >> 2;
    const int col0 = (lane & 3) * 2;
    const float li0 = 1.0f / l0, li1 = 1.0f / l1;
    const int s0 = qb*128 + w16 + g;
    const size_t yb0 = ((size_t)(b*SS + s0)*HH + h)*HD;
    const size_t yb1 = ((size_t)(b*SS + s0 + 8)*HH + h)*HD;
    #pragma unroll
    for (int nt = 0; nt < 16; nt++) {
        const int c = nt*8 + col0;
        const float x0 = oacc[nt][0]*li0, y0 = oacc[nt][1]*li0;
        const float x1 = oacc[nt][2]*li1, y1 = oacc[nt][3]*li1;
        *(uint32_t*)(g_yhi + yb0 + c) = pack_hi(x0, y0);
        *(uint32_t*)(g_ylo + yb0 + c) = pack_lo(x0, y0);
        *(uint32_t*)(g_yhi + yb1 + c) = pack_hi(x1, y1);
        *(uint32_t*)(g_ylo + yb1 + c) = pack_lo(x1, y1);
    }
}

// ---------------------------------------------------------------------------
extern "C" void kernel_launch(void* const* d_in, const int* in_sizes, int n_in,
                              void* d_out, int out_size)
{
    const float* x   = (const float*)d_in[0];
    const float* ctx = (const float*)d_in[1];
    const float* cq  = (const float*)d_in[2];
    const float* sq  = (const float*)d_in[3];
    const float* ck  = (const float*)d_in[4];
    const float* sk  = (const float*)d_in[5];
    const float* Wq  = (const float*)d_in[6];
    const float* Wk  = (const float*)d_in[7];
    const float* Wv  = (const float*)d_in[8];
    const float* Wo  = (const float*)d_in[9];
    const float* qw  = (const float*)d_in[10];
    const float* kw  = (const float*)d_in[11];
    float* out = (float*)d_out;

    cudaFuncSetAttribute(qkv_kernel, cudaFuncAttributeMaxDynamicSharedMemorySize, GEMM_DSMEM);
    cudaFuncSetAttribute(wo_kernel,  cudaFuncAttributeMaxDynamicSharedMemorySize, GEMM_DSMEM);
    cudaFuncSetAttribute(flash_mma,  cudaFuncAttributeMaxDynamicSharedMemorySize, FLASH_DSMEM);

    cvt6_kernel<<<32768, 256>>>(x, ctx, Wq, Wk, Wv, Wo);

    dim3 gq3(DM/128, NROWS/128, 3);     // (16, 32, 3)
    qkv_kernel<<<gq3, 512, GEMM_DSMEM>>>();
    rms_rope_kernel<<<dim3(BB*HH*SS, 2), HD>>>(cq, sq, ck, sk, qw, kw);
    flash_mma<<<dim3(SS/128, BB*HH), 256, FLASH_DSMEM>>>();
    dim3 gg(DM/128, NROWS/128);         // (16, 32)
    wo_kernel<<<gg, 512, GEMM_DSMEM>>>(out);
}